// round 15
// baseline (speedup 1.0000x reference)
#include <cuda_runtime.h>
#include <math.h>
#include <stdint.h>

// ---------------- problem constants ----------------
constexpr int cB  = 2;
constexpr int cL  = 4096;
constexpr int cD  = 1024;   // D_MODEL
constexpr int cKD = 768;    // KEY_DIM
constexpr int cVD = 1536;   // VALUE_DIM
constexpr int cH  = 8;
constexpr int cDK = 96;     // per-head qk dim
constexpr int cDV = 192;    // per-head v dim
constexpr int cCS = 64;     // chunk size
constexpr int cNC = cL / cCS;       // 64 chunks per sequence
constexpr int cM  = cB * cL;        // 8192 tokens
constexpr int cBH = cB * cH;        // 16
constexpr int cNP = cKD + cKD + cVD + cVD;  // 4608 packed projection width

typedef unsigned long long ull;

// ---------------- scratch (device globals; no cudaMalloc allowed) ----------------
__device__ uint32_t g_Wcat[cNP * cD];   // [Wq|Wk|Wv|Wg] TRANSPOSED (n-major), tf32 bits
__device__ uint32_t g_WoT [cD * cVD];   // Wo TRANSPOSED (n-major), tf32 bits
__device__ uint32_t g_uT  [cM * cD];    // u, tf32 bits
__device__ float g_proj[cM * cNP];      // packed projection outputs (fp32)
__device__ float g_qn [cM * cKD];   // qn; becomes qe (ROW-PAIR INTERLEAVED) after chunk_pre
__device__ float g_kn [cM * cKD];   // kn; becomes kd (row-major) after chunk_pre
__device__ float g_vh [cM * cVD];   // head layout; becomes u_ after chunk_pre
__device__ float g_kce[cM * cKD];   // kcd * exp(dec), ROW-PAIR INTERLEAVED
__device__ float g_gk [cBH * cL];
__device__ float g_bt [cBH * cL];
__device__ float g_at [cBH * cNC * cCS * cCS];  // intra-chunk attn, ROW-PAIR INTERLEAVED
__device__ float g_edl[cBH * cNC];
__device__ float g_o  [cM * cVD];   // (b,h,l,dv)
__device__ uint32_t g_on [cM * cVD];   // gated+normed, tf32 bits

// ---------------- tf32 / f32x2 helpers ----------------
__device__ __forceinline__ uint32_t f2tf32(float f)
{
    uint32_t r;
    asm("cvt.rna.tf32.f32 %0, %1;" : "=r"(r) : "f"(f));
    return r;
}

__device__ __forceinline__ void mma_tf32(float c[4], const uint32_t a[4], const uint32_t b[2])
{
    asm volatile(
        "mma.sync.aligned.m16n8k8.row.col.f32.tf32.tf32.f32 "
        "{%0,%1,%2,%3}, {%4,%5,%6,%7}, {%8,%9}, {%0,%1,%2,%3};"
        : "+f"(c[0]), "+f"(c[1]), "+f"(c[2]), "+f"(c[3])
        : "r"(a[0]), "r"(a[1]), "r"(a[2]), "r"(a[3]), "r"(b[0]), "r"(b[1]));
}

__device__ __forceinline__ ull pk2(float x)
{
    ull r;
    asm("mov.b64 %0, {%1,%1};" : "=l"(r) : "f"(x));
    return r;
}

__device__ __forceinline__ void fma2(ull& d, ull a, ull b)
{
    asm("fma.rn.f32x2 %0, %1, %2, %3;" : "=l"(d) : "l"(a), "l"(b), "l"(d));
}

__device__ __forceinline__ float2 upk2(ull v)
{
    float2 r;
    asm("mov.b64 {%0,%1}, %2;" : "=f"(r.x), "=f"(r.y) : "l"(v));
    return r;
}

#define CP16(dst, src) \
    asm volatile("cp.async.cg.shared.global [%0], [%1], 16;" :: "r"(dst), "l"(src))

#define LDSM4(r0, r1, r2, r3, addr) \
    asm volatile("ldmatrix.sync.aligned.m8n8.x4.shared.b16 {%0,%1,%2,%3}, [%4];" \
                 : "=r"(r0), "=r"(r1), "=r"(r2), "=r"(r3) : "r"(addr))

// ---------------- tf32 tensor-core GEMM (3-stage, 3 CTAs/SM = 24 warps) ----------------
constexpr int GEMM_STAGES = 3;
constexpr int GEMM_STAGE_WORDS = 128 * 20;
constexpr int GEMM_SMEM = GEMM_STAGES * 2 * GEMM_STAGE_WORDS * 4;   // 56832 B
__global__ void __launch_bounds__(256, 3)
gemm_tf32_kernel(const uint32_t* __restrict__ A, int lda,
                 const uint32_t* __restrict__ B, int ldb,
                 float* __restrict__ C, int ldc,
                 int M, int N, int K)
{
    extern __shared__ uint32_t smem_u[];
    uint32_t* As = smem_u;
    uint32_t* Bs = smem_u + GEMM_STAGES * GEMM_STAGE_WORDS;

    const int tid  = threadIdx.x;
    const int wid  = tid >> 5;
    const int lane = tid & 31;
    const int g    = lane >> 2;
    const int t    = lane & 3;
    const int wm   = (wid >> 2) * 64;
    const int wn   = (wid & 3) * 32;

    const int bm = blockIdx.y * 128;
    const int bn = blockIdx.x * 128;

    const int row = tid >> 1;
    const int cb  = (tid & 1) * 8;
    const uint32_t* Ag = A + (size_t)(bm + row) * lda + cb;
    const uint32_t* Bg = B + (size_t)(bn + row) * ldb + cb;

    const uint32_t sA0 = (uint32_t)__cvta_generic_to_shared(As + row * 20 + cb);
    const uint32_t sB0 = (uint32_t)__cvta_generic_to_shared(Bs + row * 20 + cb);
    constexpr uint32_t STG_B = GEMM_STAGE_WORDS * 4;

    const int rA = wm + ((lane >> 3) & 1) * 8 + (lane & 7);
    const int cA = (lane >> 4) * 4;
    const int rB = wn + (lane >> 4) * 8 + (lane & 7);
    const int cB2 = ((lane >> 3) & 1) * 4;
    const uint32_t lA0 = (uint32_t)__cvta_generic_to_shared(As + rA * 20 + cA);
    const uint32_t lB0 = (uint32_t)__cvta_generic_to_shared(Bs + rB * 20 + cB2);

    float acc[4][4][4];
#pragma unroll
    for (int i = 0; i < 4; i++)
#pragma unroll
        for (int j = 0; j < 4; j++)
#pragma unroll
            for (int r = 0; r < 4; r++) acc[i][j][r] = 0.f;

    const int nt = K >> 4;

#pragma unroll
    for (int s = 0; s < GEMM_STAGES - 1; s++) {
        const uint32_t* a = Ag + (size_t)s * 16;
        const uint32_t* b = Bg + (size_t)s * 16;
        CP16(sA0 + s * STG_B, a); CP16(sA0 + s * STG_B + 16, a + 4);
        CP16(sB0 + s * STG_B, b); CP16(sB0 + s * STG_B + 16, b + 4);
        asm volatile("cp.async.commit_group;");
    }

    int buf = 0;
    for (int kt = 0; kt < nt; kt++) {
        asm volatile("cp.async.wait_group 1;");
        __syncthreads();

        const uint32_t offA = lA0 + buf * STG_B;
        const uint32_t offB = lB0 + buf * STG_B;
#pragma unroll
        for (int ks = 0; ks < 16; ks += 8) {
            uint32_t af[4][4], bf[4][2];
#pragma unroll
            for (int mi = 0; mi < 4; mi++)
                LDSM4(af[mi][0], af[mi][1], af[mi][2], af[mi][3],
                      offA + mi * (16 * 20 * 4) + ks * 4);
#pragma unroll
            for (int np = 0; np < 2; np++)
                LDSM4(bf[2 * np][0], bf[2 * np][1], bf[2 * np + 1][0], bf[2 * np + 1][1],
                      offB + np * (16 * 20 * 4) + ks * 4);
#pragma unroll
            for (int mi = 0; mi < 4; mi++)
#pragma unroll
                for (int ni = 0; ni < 4; ni++)
                    mma_tf32(acc[mi][ni], af[mi], bf[ni]);
        }

        if (kt + GEMM_STAGES - 1 < nt) {
            int s = kt + GEMM_STAGES - 1;
            int sb = s % GEMM_STAGES;
            const uint32_t* a = Ag + (size_t)s * 16;
            const uint32_t* b = Bg + (size_t)s * 16;
            CP16(sA0 + sb * STG_B, a); CP16(sA0 + sb * STG_B + 16, a + 4);
            CP16(sB0 + sb * STG_B, b); CP16(sB0 + sb * STG_B + 16, b + 4);
        }
        asm volatile("cp.async.commit_group;");
        if (++buf == GEMM_STAGES) buf = 0;
    }

#pragma unroll
    for (int mi = 0; mi < 4; mi++) {
#pragma unroll
        for (int ni = 0; ni < 4; ni++) {
            int row0 = bm + wm + mi * 16 + g;
            int col  = bn + wn + ni * 8 + 2 * t;
            *(float2*)(C + (size_t)row0 * ldc + col) = make_float2(acc[mi][ni][0], acc[mi][ni][1]);
            *(float2*)(C + (size_t)(row0 + 8) * ldc + col) = make_float2(acc[mi][ni][2], acc[mi][ni][3]);
        }
    }
}

// ---------------- pack [Wq|Wk|Wv|Wg] TRANSPOSED (n-major) tf32 ----------------
__global__ void pack_w_kernel(const float* __restrict__ Wq, const float* __restrict__ Wk,
                              const float* __restrict__ Wv, const float* __restrict__ Wg)
{
    int idx = blockIdx.x * blockDim.x + threadIdx.x;
    if (idx >= cNP * cD) return;
    int n = idx / cD, k = idx % cD;
    float v;
    if (n < cKD)                 v = Wq[k * cKD + n];
    else if (n < 2 * cKD)        v = Wk[k * cKD + (n - cKD)];
    else if (n < 2 * cKD + cVD)  v = Wv[k * cVD + (n - 2 * cKD)];
    else                         v = Wg[k * cVD + (n - 2 * cKD - cVD)];
    g_Wcat[idx] = f2tf32(v);
}

__global__ void pack_wo_kernel(const float* __restrict__ Wo)
{
    int idx = blockIdx.x * blockDim.x + threadIdx.x;
    if (idx >= cD * cVD) return;
    int n = idx / cVD, k = idx % cVD;
    g_WoT[idx] = f2tf32(Wo[k * cD + n]);
}

__global__ void convert_u_kernel(const float4* __restrict__ u4)
{
    int idx = blockIdx.x * blockDim.x + threadIdx.x;
    if (idx >= cM * cD / 4) return;
    float4 v = u4[idx];
    uint4 r;
    r.x = f2tf32(v.x); r.y = f2tf32(v.y); r.z = f2tf32(v.z); r.w = f2tf32(v.w);
    ((uint4*)g_uT)[idx] = r;
}

// ---------------- gk / beta projections: warp per token, W in smem ----------------
__global__ void proj_gates_kernel(const float* __restrict__ u, const float* __restrict__ Wgk,
                                  const float* __restrict__ Wb, const float* __restrict__ b_b,
                                  const float* __restrict__ A_log, const float* __restrict__ dt_bias)
{
    extern __shared__ float sW[];   // [1024][16]
    const int tid = threadIdx.x;
    const int wid = tid >> 5;
    const int lane = tid & 31;

    for (int idx = tid; idx < cD * 16; idx += 256) {
        int i = idx >> 4, c = idx & 15;
        sW[idx] = (c < 8) ? Wgk[i * cH + c] : Wb[i * cH + (c - 8)];
    }
    __syncthreads();

    int m = blockIdx.x * 8 + wid;
    const float* ur = u + (size_t)m * cD;
    float s[16];
#pragma unroll
    for (int c = 0; c < 16; c++) s[c] = 0.f;
    for (int j = 0; j < 32; j++) {
        int i = lane + 32 * j;
        float uv = __ldg(ur + i);
        const float* wr = sW + i * 16;
#pragma unroll
        for (int c = 0; c < 16; c++) s[c] += uv * wr[c];
    }
#pragma unroll
    for (int c = 0; c < 16; c++) {
#pragma unroll
        for (int o = 16; o; o >>= 1) s[c] += __shfl_xor_sync(0xffffffffu, s[c], o);
    }
    if (lane < 8) {
        int h = lane;
        float x  = s[h] + dt_bias[h];
        float sp = (x > 20.f) ? x : log1pf(expf(x));
        float gkv = -expf(A_log[h]) * sp;
        int b = m / cL, l = m % cL;
        g_gk[((size_t)(b * cH + h)) * cL + l] = gkv;
    } else {
        int h = lane - 8;
        float bv = 1.f / (1.f + expf(-(s[8 + h] + b_b[h])));
        int b = m / cL, l = m % cL;
        g_bt[((size_t)(b * cH + h)) * cL + l] = bv;
    }
}

// ---------------- fused conv + SiLU + L2norm for q,k; writes head layout ----------------
__global__ void conv_qk_norm_kernel(const float* __restrict__ wq, const float* __restrict__ wk)
{
    int gw = (blockIdx.x * blockDim.x + threadIdx.x) >> 5;
    int lane = threadIdx.x & 31;
    if (gw >= cM * cH) return;
    int m = gw / cH, h = gw % cH;
    int b = m / cL, l = m % cL;
    const size_t rowbase = (size_t)(m - l) * cNP;

    float qv[3], kv[3];
    float ssq = 0.f, ssk = 0.f;
#pragma unroll
    for (int r = 0; r < 3; r++) {
        int c = h * cDK + lane + 32 * r;
        float aq = 0.f, ak = 0.f;
#pragma unroll
        for (int j = 0; j < 4; j++) {
            int ll = l - 3 + j;
            if (ll >= 0) {
                const float* rowp = g_proj + rowbase + (size_t)ll * cNP;
                aq += rowp[c]       * wq[c * 4 + j];
                ak += rowp[cKD + c] * wk[c * 4 + j];
            }
        }
        aq = aq / (1.f + expf(-aq));
        ak = ak / (1.f + expf(-ak));
        qv[r] = aq; kv[r] = ak;
        ssq += aq * aq; ssk += ak * ak;
    }
#pragma unroll
    for (int o = 16; o; o >>= 1) {
        ssq += __shfl_xor_sync(0xffffffffu, ssq, o);
        ssk += __shfl_xor_sync(0xffffffffu, ssk, o);
    }
    float iq = 1.f / fmaxf(sqrtf(ssq), 1e-12f);
    float ik = 1.f / fmaxf(sqrtf(ssk), 1e-12f);
    float* dq = g_qn + ((size_t)(b * cH + h) * cL + l) * cDK;
    float* dk = g_kn + ((size_t)(b * cH + h) * cL + l) * cDK;
#pragma unroll
    for (int r = 0; r < 3; r++) {
        dq[lane + 32 * r] = qv[r] * iq;
        dk[lane + 32 * r] = kv[r] * ik;
    }
}

// ---------------- conv + SiLU for v; writes head layout directly ----------------
__global__ void conv_v_kernel(const float* __restrict__ wv)
{
    int idx = blockIdx.x * blockDim.x + threadIdx.x;
    if (idx >= cM * cVD) return;
    int c = idx % cVD;
    int m = idx / cVD;
    int l = m % cL, b = m / cL;
    float acc = 0.f;
#pragma unroll
    for (int j = 0; j < 4; j++) {
        int ll = l - 3 + j;
        if (ll >= 0) acc += g_proj[(size_t)(m - l + ll) * cNP + 2 * cKD + c] * wv[c * 4 + j];
    }
    int h = c / cDV, d = c % cDV;
    g_vh[((size_t)(b * cH + h) * cL + l) * cDV + d] = acc / (1.f + expf(-acc));
}

// ---------------- per-chunk precompute (R10: sk padded stride 100; interleaved outputs) ----------------
constexpr int cSKS = 100;
constexpr int CP_SMEM_FLOATS = 6144 + 64 * cSKS + 6144 + 4096 + 4096 + 12288 + 64 + 64;
constexpr int CP_THREADS = 320;
__global__ void chunk_pre_kernel()
{
    extern __shared__ float sm[];
    float* sq   = sm;                    // 64 x 96
    float* sk   = sq + 6144;             // 64 x 100 (padded)
    float* skb  = sk + 64 * cSKS;        // 64 x 96
    float* sKK  = skb + 6144;            // 64 x 64
    float* sM   = sKK + 4096;            // 64 x 64
    float* sv   = sM + 4096;             // 64 x 192
    float* sdec = sv + 12288;
    float* sbet = sdec + 64;

    const int tid = threadIdx.x;
    const int cid = blockIdx.x;
    const int bh = cid / cNC;
    const int n  = cid % cNC;
    const size_t cbg  = (size_t)bh * cL + n * cCS;
    const size_t cb96  = cbg * cDK;
    const size_t cb192 = cbg * cDV;
    const float scale = rsqrtf((float)cDK);

    for (int i4 = tid; i4 < 1536; i4 += CP_THREADS) {
        ((float4*)sq)[i4] = ((const float4*)(g_qn + cb96))[i4];
        int c = i4 / 24, d4 = i4 % 24;
        ((float4*)sk)[c * (cSKS / 4) + d4] = ((const float4*)(g_kn + cb96))[i4];
    }
    if (tid < 64) sbet[tid] = g_bt[cbg + tid];
    if (tid < 32) {
        float x0 = g_gk[cbg + tid], x1 = g_gk[cbg + 32 + tid];
#pragma unroll
        for (int o = 1; o < 32; o <<= 1) {
            float y = __shfl_up_sync(0xffffffffu, x0, o);
            if (tid >= o) x0 += y;
        }
        float t0 = __shfl_sync(0xffffffffu, x0, 31);
#pragma unroll
        for (int o = 1; o < 32; o <<= 1) {
            float y = __shfl_up_sync(0xffffffffu, x1, o);
            if (tid >= o) x1 += y;
        }
        sdec[tid] = x0;
        sdec[32 + tid] = x1 + t0;
    }
    __syncthreads();
    const float dl = sdec[63];

    for (int i = tid; i < 6144; i += CP_THREADS) {
        int c = i / cDK, d = i - c * cDK;
        skb[i] = sk[c * cSKS + d] * sbet[c];
    }
    for (int i = tid; i < 12288; i += CP_THREADS) sv[i]  = g_vh[cb192 + i] * sbet[i / cDV];

    // qe: ROW-PAIR INTERLEAVED [(c>>1)][d][c&1]; kd: row-major
    for (int i = tid; i < 6144; i += CP_THREADS) {
        int c = i / cDK, d = i - c * cDK;
        g_qn[cb96 + (size_t)(c >> 1) * 192 + 2 * d + (c & 1)] = sq[i] * scale * expf(sdec[c]);
        g_kn[cb96 + i] = sk[c * cSKS + d] * expf(dl - sdec[c]);
    }
    __syncthreads();

    for (int idx = tid; idx < 4096; idx += CP_THREADS) {
        int i = idx >> 6, j = idx & 63;
        float s = 0.f;
        const float4* a4 = (const float4*)(skb + i * cDK);
        const float4* b4 = (const float4*)(sk + j * cSKS);
#pragma unroll 6
        for (int d = 0; d < cDK / 4; d++) {
            float4 a = a4[d], b = b4[d];
            s += a.x * b.x + a.y * b.y + a.z * b.z + a.w * b.w;
        }
        sKK[idx] = s;
    }
    // intra-chunk attn -> ROW-PAIR INTERLEAVED
    for (int idx = tid; idx < 4096; idx += CP_THREADS) {
        int i = idx >> 6, j = idx & 63;
        float a = 0.f;
        if (i >= j) {
            float s = 0.f;
            const float4* a4 = (const float4*)(sq + i * cDK);
            const float4* b4 = (const float4*)(sk + j * cSKS);
#pragma unroll 6
            for (int d = 0; d < cDK / 4; d++) {
                float4 x = a4[d], y = b4[d];
                s += x.x * y.x + x.y * y.y + x.z * y.z + x.w * y.w;
            }
            a = s * scale * expf(sdec[i] - sdec[j]);
        }
        g_at[(size_t)cid * 4096 + (size_t)(i >> 1) * 128 + 2 * j + (i & 1)] = a;
    }
    for (int idx = tid; idx < 4096; idx += CP_THREADS) {
        int i = idx >> 6, j = idx & 63;
        sM[idx] = (i > j) ? sKK[idx] * expf(sdec[i] - sdec[j]) : 0.f;
    }
    __syncthreads();

    for (int i = 1; i < 64; i++) {
        if (tid < 192) {
            float s = 0.f;
            const float* mrow = sM + i * 64;
            int j = 0;
            for (; j + 4 <= i; j += 4) {
                float4 m4 = *(const float4*)(mrow + j);
                s += m4.x * sv[(j + 0) * 192 + tid] + m4.y * sv[(j + 1) * 192 + tid]
                   + m4.z * sv[(j + 2) * 192 + tid] + m4.w * sv[(j + 3) * 192 + tid];
            }
            for (; j < i; j++) s += mrow[j] * sv[j * 192 + tid];
            sv[i * 192 + tid] -= s;
        } else if (tid < 288) {
            int c = tid - 192;
            float s = 0.f;
            const float* krow = sKK + i * 64;
            int j = 0;
            for (; j + 4 <= i; j += 4) {
                float4 m4 = *(const float4*)(krow + j);
                s += m4.x * skb[(j + 0) * 96 + c] + m4.y * skb[(j + 1) * 96 + c]
                   + m4.z * skb[(j + 2) * 96 + c] + m4.w * skb[(j + 3) * 96 + c];
            }
            for (; j < i; j++) s += krow[j] * skb[j * 96 + c];
            skb[i * 96 + c] -= s;
        }
        __syncthreads();
    }

    for (int i = tid; i < 12288; i += CP_THREADS) g_vh[cb192 + i] = sv[i];
    // kce: ROW-PAIR INTERLEAVED
    for (int i = tid; i < 6144; i += CP_THREADS) {
        int c = i / cDK, d = i - c * cDK;
        g_kce[cb96 + (size_t)(c >> 1) * 192 + 2 * d + (c & 1)] = skb[i] * expf(sdec[c]);
    }
    if (tid == 0) g_edl[cid] = expf(dl);
}

// ---------------- sequential scan: R10 (smem-staged + f32x2, validated) ----------------
constexpr int SC_SMEM_FLOATS = 3 * 6144 + 4096 + 2048 + 3072;
constexpr int SC_THREADS = 512;
__global__ void __launch_bounds__(SC_THREADS, 1)
scan_kernel()
{
    extern __shared__ float sm[];
    float* sqe  = sm;              // interleaved [rp][192]
    float* skce = sqe + 6144;      // interleaved [rp][192]
    float* skd  = skce + 6144;     // row-major   [c][96]
    float* sat  = skd + 6144;      // interleaved [rp][128]
    float* svn  = sat + 4096;      // [c][32]
    float* S    = svn + 2048;      // [d][32]

    const int tid = threadIdx.x;
    const int bh = blockIdx.y;
    const int e0 = blockIdx.x * 32;
    const int e  = tid & 31;
    const int w  = tid >> 5;        // 0..15
    const int c0 = w * 4;
    const int rp0 = w * 2;
    const int d0 = w * 6;

    for (int i = tid; i < 3072; i += SC_THREADS) S[i] = 0.f;

    for (int n = 0; n < cNC; n++) {
        const size_t cbg = (size_t)bh * cL + n * cCS;
        const size_t cb96 = cbg * cDK;
        const size_t cb192 = cbg * cDV;
        __syncthreads();
        for (int i = tid; i < 1536; i += SC_THREADS) {
            ((float4*)sqe)[i]  = ((const float4*)(g_qn + cb96))[i];
            ((float4*)skce)[i] = ((const float4*)(g_kce + cb96))[i];
            ((float4*)skd)[i]  = ((const float4*)(g_kn + cb96))[i];
        }
        for (int i = tid; i < 1024; i += SC_THREADS)
            ((float4*)sat)[i] = ((const float4*)(g_at + (size_t)(bh * cNC + n) * 4096))[i];
        __syncthreads();

        // ---- phase A: accv = kce@S, acco = qe@S ----
        ull accv0 = 0, accv1 = 0, acco0 = 0, acco1 = 0;
        const ulonglong2* q0 = (const ulonglong2*)(sqe + rp0 * 192);
        const ulonglong2* q1 = (const ulonglong2*)(sqe + (rp0 + 1) * 192);
        const ulonglong2* k0p = (const ulonglong2*)(skce + rp0 * 192);
        const ulonglong2* k1p = (const ulonglong2*)(skce + (rp0 + 1) * 192);
#pragma unroll 6
        for (int jg = 0; jg < 24; jg++) {
            const int j = jg * 4;
            ull b0 = pk2(S[(j + 0) * 32 + e]);
            ull b1 = pk2(S[(j + 1) * 32 + e]);
            ull b2 = pk2(S[(j + 2) * 32 + e]);
            ull b3 = pk2(S[(j + 3) * 32 + e]);
            ulonglong2 qa = q0[2 * jg], qb = q0[2 * jg + 1];
            ulonglong2 ra = q1[2 * jg], rb = q1[2 * jg + 1];
            ulonglong2 ca = k0p[2 * jg], cbv = k0p[2 * jg + 1];
            ulonglong2 da = k1p[2 * jg], db = k1p[2 * jg + 1];
            fma2(acco0, qa.x, b0); fma2(acco0, qa.y, b1); fma2(acco0, qb.x, b2); fma2(acco0, qb.y, b3);
            fma2(acco1, ra.x, b0); fma2(acco1, ra.y, b1); fma2(acco1, rb.x, b2); fma2(acco1, rb.y, b3);
            fma2(accv0, ca.x, b0); fma2(accv0, ca.y, b1); fma2(accv0, cbv.x, b2); fma2(accv0, cbv.y, b3);
            fma2(accv1, da.x, b0); fma2(accv1, da.y, b1); fma2(accv1, db.x, b2); fma2(accv1, db.y, b3);
        }
        {
            float su0 = __ldg(g_vh + cb192 + (size_t)(c0 + 0) * cDV + e0 + e);
            float su1 = __ldg(g_vh + cb192 + (size_t)(c0 + 1) * cDV + e0 + e);
            float su2 = __ldg(g_vh + cb192 + (size_t)(c0 + 2) * cDV + e0 + e);
            float su3 = __ldg(g_vh + cb192 + (size_t)(c0 + 3) * cDV + e0 + e);
            float2 v01 = upk2(accv0);
            float2 v23 = upk2(accv1);
            svn[(c0 + 0) * 32 + e] = su0 - v01.x;
            svn[(c0 + 1) * 32 + e] = su1 - v01.y;
            svn[(c0 + 2) * 32 + e] = su2 - v23.x;
            svn[(c0 + 3) * 32 + e] = su3 - v23.y;
        }
        __syncthreads();

        // ---- phase B: o += attn@v_new ; accS = kd^T@v_new ----
        const float el = __ldg(g_edl + bh * cNC + n);
        ull accS0 = 0, accS1 = 0, accS2 = 0;
        const ulonglong2* a0 = (const ulonglong2*)(sat + rp0 * 128);
        const ulonglong2* a1 = (const ulonglong2*)(sat + (rp0 + 1) * 128);
#pragma unroll 8
        for (int c = 0; c < 64; c += 2) {
            ull bva = pk2(svn[c * 32 + e]);
            ull bvb = pk2(svn[(c + 1) * 32 + e]);
            ulonglong2 v0 = a0[c >> 1];
            ulonglong2 v1 = a1[c >> 1];
            fma2(acco0, v0.x, bva); fma2(acco0, v0.y, bvb);
            fma2(acco1, v1.x, bva); fma2(acco1, v1.y, bvb);
            const ull* kr0 = (const ull*)(skd + (size_t)c * cDK + d0);
            const ull* kr1 = (const ull*)(skd + (size_t)(c + 1) * cDK + d0);
            fma2(accS0, kr0[0], bva); fma2(accS1, kr0[1], bva); fma2(accS2, kr0[2], bva);
            fma2(accS0, kr1[0], bvb); fma2(accS1, kr1[1], bvb); fma2(accS2, kr1[2], bvb);
        }
        {
            float2 o01 = upk2(acco0);
            float2 o23 = upk2(acco1);
            g_o[cb192 + (size_t)(c0 + 0) * cDV + e0 + e] = o01.x;
            g_o[cb192 + (size_t)(c0 + 1) * cDV + e0 + e] = o01.y;
            g_o[cb192 + (size_t)(c0 + 2) * cDV + e0 + e] = o23.x;
            g_o[cb192 + (size_t)(c0 + 3) * cDV + e0 + e] = o23.y;
        }
        {
            float2 s01 = upk2(accS0);
            float2 s23 = upk2(accS1);
            float2 s45 = upk2(accS2);
            int i0 = d0 * 32 + e;
            S[i0]       = S[i0] * el + s01.x;
            S[i0 + 32]  = S[i0 + 32] * el + s01.y;
            S[i0 + 64]  = S[i0 + 64] * el + s23.x;
            S[i0 + 96]  = S[i0 + 96] * el + s23.y;
            S[i0 + 128] = S[i0 + 128] * el + s45.x;
            S[i0 + 160] = S[i0 + 160] * el + s45.y;
        }
    }
}

// ---------------- gated RMS norm + transpose back (writes tf32 bits) ----------------
__global__ void gate_norm_kernel(const float* __restrict__ norm_w)
{
    int gw = (blockIdx.x * blockDim.x + threadIdx.x) >> 5;
    int lane = threadIdx.x & 31;
    if (gw >= cM * cH) return;
    int m = gw / cH, h = gw % cH;
    int b = m / cL, l = m % cL;
    const float* orow = g_o + ((size_t)(b * cH + h) * cL + l) * cDV;
    float vals[6];
    float ss = 0.f;
#pragma unroll
    for (int k = 0; k < 6; k++) {
        float v = orow[lane + 32 * k];
        vals[k] = v;
        ss += v * v;
    }
#pragma unroll
    for (int o = 16; o; o >>= 1) ss += __shfl_xor_sync(0xffffffffu, ss, o);
    float r = 1.f / sqrtf(ss / (float)cDV + 1e-5f);
#pragma unroll
    for (int k = 0; k < 6; k++) {
        int d = lane + 32 * k;
        float gg = g_proj[(size_t)m * cNP + 2 * cKD + cVD + h * cDV + d];
        float sg = gg / (1.f + expf(-gg));
        g_on[(size_t)m * cVD + h * cDV + d] = f2tf32(vals[k] * r * norm_w[d] * sg);
    }
}

// ---------------- host launch ----------------
template <typename T>
static T* sym(const void* symbol)
{
    void* p = nullptr;
    cudaGetSymbolAddress(&p, symbol);
    return (T*)p;
}

extern "C" void kernel_launch(void* const* d_in, const int* in_sizes, int n_in,
                              void* d_out, int out_size)
{
    const float* u       = (const float*)d_in[0];
    const float* Wq      = (const float*)d_in[1];
    const float* Wk      = (const float*)d_in[2];
    const float* Wv      = (const float*)d_in[3];
    const float* Wg      = (const float*)d_in[4];
    const float* Wo      = (const float*)d_in[5];
    const float* Wgk     = (const float*)d_in[6];
    const float* Wb      = (const float*)d_in[7];
    const float* b_b     = (const float*)d_in[8];
    const float* A_log   = (const float*)d_in[9];
    const float* dt_bias = (const float*)d_in[10];
    const float* conv_q  = (const float*)d_in[11];
    const float* conv_k  = (const float*)d_in[12];
    const float* conv_v  = (const float*)d_in[13];
    const float* norm_w  = (const float*)d_in[14];
    float* out = (float*)d_out;

    uint32_t* Wcat = sym<uint32_t>(g_Wcat);
    uint32_t* WoT  = sym<uint32_t>(g_WoT);
    uint32_t* uT   = sym<uint32_t>(g_uT);
    uint32_t* on   = sym<uint32_t>(g_on);
    float* proj = sym<float>(g_proj);

    cudaFuncSetAttribute(gemm_tf32_kernel, cudaFuncAttributeMaxDynamicSharedMemorySize, GEMM_SMEM);
    cudaFuncSetAttribute(chunk_pre_kernel, cudaFuncAttributeMaxDynamicSharedMemorySize,
                         CP_SMEM_FLOATS * (int)sizeof(float));
    cudaFuncSetAttribute(scan_kernel, cudaFuncAttributeMaxDynamicSharedMemorySize,
                         SC_SMEM_FLOATS * (int)sizeof(float));
    cudaFuncSetAttribute(proj_gates_kernel, cudaFuncAttributeMaxDynamicSharedMemorySize, 65536);

    // pack/convert (B operands transposed to n-major)
    pack_w_kernel<<<(cNP * cD + 255) / 256, 256>>>(Wq, Wk, Wv, Wg);
    convert_u_kernel<<<(cM * cD / 4 + 255) / 256, 256>>>((const float4*)u);
    pack_wo_kernel<<<(cD * cVD + 255) / 256, 256>>>(Wo);

    // fused projection GEMM (q|k|v|g)
    gemm_tf32_kernel<<<dim3(cNP / 128, cM / 128), 256, GEMM_SMEM>>>(
        uT, cD, Wcat, cD, proj, cNP, cM, cNP, cD);

    // gates
    proj_gates_kernel<<<cM / 8, 256, 65536>>>(u, Wgk, Wb, b_b, A_log, dt_bias);

    // fused conv+silu(+l2norm) -> head layouts
    conv_qk_norm_kernel<<<(cM * cH * 32 + 255) / 256, 256>>>(conv_q, conv_k);
    conv_v_kernel<<<(cM * cVD + 255) / 256, 256>>>(conv_v);

    // delta-rule chunk precompute + scan
    chunk_pre_kernel<<<cBH * cNC, CP_THREADS, CP_SMEM_FLOATS * sizeof(float)>>>();
    scan_kernel<<<dim3(6, cBH), SC_THREADS, SC_SMEM_FLOATS * sizeof(float)>>>();

    // gated rms norm + output projection
    gate_norm_kernel<<<(cM * cH * 32 + 255) / 256, 256>>>(norm_w);
    gemm_tf32_kernel<<<dim3(cD / 128, cM / 128), 256, GEMM_SMEM>>>(
        on, cVD, WoT, cVD, out, cD, cM, cD, cVD);
}

// round 16
// speedup vs baseline: 1.2566x; 1.2566x over previous
#include <cuda_runtime.h>
#include <math.h>
#include <stdint.h>

// ---------------- problem constants ----------------
constexpr int cB  = 2;
constexpr int cL  = 4096;
constexpr int cD  = 1024;   // D_MODEL
constexpr int cKD = 768;    // KEY_DIM
constexpr int cVD = 1536;   // VALUE_DIM
constexpr int cH  = 8;
constexpr int cDK = 96;     // per-head qk dim
constexpr int cDV = 192;    // per-head v dim
constexpr int cCS = 64;     // chunk size
constexpr int cNC = cL / cCS;       // 64 chunks per sequence
constexpr int cM  = cB * cL;        // 8192 tokens
constexpr int cBH = cB * cH;        // 16
constexpr int cNP = cKD + cKD + cVD + cVD;  // 4608 packed projection width

typedef unsigned long long ull;

// ---------------- scratch (device globals; no cudaMalloc allowed) ----------------
__device__ uint32_t g_Wcat[cNP * cD];   // [Wq|Wk|Wv|Wg] TRANSPOSED (n-major), tf32 bits
__device__ uint32_t g_WoT [cD * cVD];   // Wo TRANSPOSED (n-major), tf32 bits
__device__ uint32_t g_uT  [cM * cD];    // u, tf32 bits
__device__ float g_proj[cM * cNP];      // packed projection outputs (fp32)
__device__ float g_qn [cM * cKD];   // qn; becomes qe (ROW-PAIR INTERLEAVED) after chunk_pre
__device__ float g_kn [cM * cKD];   // kn; becomes kd (row-major) after chunk_pre
__device__ float g_vh [cM * cVD];   // head layout; becomes u_ after chunk_pre
__device__ float g_kce[cM * cKD];   // kcd * exp(dec), ROW-PAIR INTERLEAVED
__device__ float g_gk [cBH * cL];
__device__ float g_bt [cBH * cL];
__device__ float g_at [cBH * cNC * cCS * cCS];  // intra-chunk attn, ROW-PAIR INTERLEAVED
__device__ float g_edl[cBH * cNC];
__device__ float g_o  [cM * cVD];   // (b,h,l,dv)
__device__ uint32_t g_on [cM * cVD];   // gated+normed, tf32 bits

// ---------------- tf32 / f32x2 helpers ----------------
__device__ __forceinline__ uint32_t f2tf32(float f)
{
    uint32_t r;
    asm("cvt.rna.tf32.f32 %0, %1;" : "=r"(r) : "f"(f));
    return r;
}

__device__ __forceinline__ void mma_tf32(float c[4], const uint32_t a[4], const uint32_t b[2])
{
    asm volatile(
        "mma.sync.aligned.m16n8k8.row.col.f32.tf32.tf32.f32 "
        "{%0,%1,%2,%3}, {%4,%5,%6,%7}, {%8,%9}, {%0,%1,%2,%3};"
        : "+f"(c[0]), "+f"(c[1]), "+f"(c[2]), "+f"(c[3])
        : "r"(a[0]), "r"(a[1]), "r"(a[2]), "r"(a[3]), "r"(b[0]), "r"(b[1]));
}

__device__ __forceinline__ ull pk2(float x)
{
    ull r;
    asm("mov.b64 %0, {%1,%1};" : "=l"(r) : "f"(x));
    return r;
}

__device__ __forceinline__ void fma2(ull& d, ull a, ull b)
{
    asm("fma.rn.f32x2 %0, %1, %2, %3;" : "=l"(d) : "l"(a), "l"(b), "l"(d));
}

__device__ __forceinline__ float2 upk2(ull v)
{
    float2 r;
    asm("mov.b64 {%0,%1}, %2;" : "=f"(r.x), "=f"(r.y) : "l"(v));
    return r;
}

#define CP16(dst, src) \
    asm volatile("cp.async.cg.shared.global [%0], [%1], 16;" :: "r"(dst), "l"(src))

#define LDSM4(r0, r1, r2, r3, addr) \
    asm volatile("ldmatrix.sync.aligned.m8n8.x4.shared.b16 {%0,%1,%2,%3}, [%4];" \
                 : "=r"(r0), "=r"(r1), "=r"(r2), "=r"(r3) : "r"(addr))

// ---------------- tf32 tensor-core GEMM (R10: 4-stage, 2 CTAs/SM, k16, ROWW 20) ----------------
constexpr int GEMM_STAGES = 4;
constexpr int GEMM_STAGE_WORDS = 128 * 20;
constexpr int GEMM_SMEM = GEMM_STAGES * 2 * GEMM_STAGE_WORDS * 4;
__global__ void __launch_bounds__(256, 2)
gemm_tf32_kernel(const uint32_t* __restrict__ A, int lda,
                 const uint32_t* __restrict__ B, int ldb,
                 float* __restrict__ C, int ldc,
                 int M, int N, int K)
{
    extern __shared__ uint32_t smem_u[];
    uint32_t* As = smem_u;
    uint32_t* Bs = smem_u + GEMM_STAGES * GEMM_STAGE_WORDS;

    const int tid  = threadIdx.x;
    const int wid  = tid >> 5;
    const int lane = tid & 31;
    const int g    = lane >> 2;
    const int t    = lane & 3;
    const int wm   = (wid >> 2) * 64;
    const int wn   = (wid & 3) * 32;

    const int bm = blockIdx.y * 128;
    const int bn = blockIdx.x * 128;

    const int row = tid >> 1;
    const int cb  = (tid & 1) * 8;
    const uint32_t* Ag = A + (size_t)(bm + row) * lda + cb;
    const uint32_t* Bg = B + (size_t)(bn + row) * ldb + cb;

    const uint32_t sA0 = (uint32_t)__cvta_generic_to_shared(As + row * 20 + cb);
    const uint32_t sB0 = (uint32_t)__cvta_generic_to_shared(Bs + row * 20 + cb);
    constexpr uint32_t STG_B = GEMM_STAGE_WORDS * 4;

    const int rA = wm + ((lane >> 3) & 1) * 8 + (lane & 7);
    const int cA = (lane >> 4) * 4;
    const int rB = wn + (lane >> 4) * 8 + (lane & 7);
    const int cB2 = ((lane >> 3) & 1) * 4;
    const uint32_t lA0 = (uint32_t)__cvta_generic_to_shared(As + rA * 20 + cA);
    const uint32_t lB0 = (uint32_t)__cvta_generic_to_shared(Bs + rB * 20 + cB2);

    float acc[4][4][4];
#pragma unroll
    for (int i = 0; i < 4; i++)
#pragma unroll
        for (int j = 0; j < 4; j++)
#pragma unroll
            for (int r = 0; r < 4; r++) acc[i][j][r] = 0.f;

    const int nt = K >> 4;

#pragma unroll
    for (int s = 0; s < GEMM_STAGES - 1; s++) {
        const uint32_t* a = Ag + (size_t)s * 16;
        const uint32_t* b = Bg + (size_t)s * 16;
        CP16(sA0 + s * STG_B, a); CP16(sA0 + s * STG_B + 16, a + 4);
        CP16(sB0 + s * STG_B, b); CP16(sB0 + s * STG_B + 16, b + 4);
        asm volatile("cp.async.commit_group;");
    }

    for (int kt = 0; kt < nt; kt++) {
        asm volatile("cp.async.wait_group 2;");
        __syncthreads();

        const int buf = kt & (GEMM_STAGES - 1);
        const uint32_t offA = lA0 + buf * STG_B;
        const uint32_t offB = lB0 + buf * STG_B;
#pragma unroll
        for (int ks = 0; ks < 16; ks += 8) {
            uint32_t af[4][4], bf[4][2];
#pragma unroll
            for (int mi = 0; mi < 4; mi++)
                LDSM4(af[mi][0], af[mi][1], af[mi][2], af[mi][3],
                      offA + mi * (16 * 20 * 4) + ks * 4);
#pragma unroll
            for (int np = 0; np < 2; np++)
                LDSM4(bf[2 * np][0], bf[2 * np][1], bf[2 * np + 1][0], bf[2 * np + 1][1],
                      offB + np * (16 * 20 * 4) + ks * 4);
#pragma unroll
            for (int mi = 0; mi < 4; mi++)
#pragma unroll
                for (int ni = 0; ni < 4; ni++)
                    mma_tf32(acc[mi][ni], af[mi], bf[ni]);
        }

        if (kt + GEMM_STAGES - 1 < nt) {
            const int s = (kt + GEMM_STAGES - 1) & (GEMM_STAGES - 1);
            const uint32_t* a = Ag + (size_t)(kt + GEMM_STAGES - 1) * 16;
            const uint32_t* b = Bg + (size_t)(kt + GEMM_STAGES - 1) * 16;
            CP16(sA0 + s * STG_B, a); CP16(sA0 + s * STG_B + 16, a + 4);
            CP16(sB0 + s * STG_B, b); CP16(sB0 + s * STG_B + 16, b + 4);
        }
        asm volatile("cp.async.commit_group;");
    }

#pragma unroll
    for (int mi = 0; mi < 4; mi++) {
#pragma unroll
        for (int ni = 0; ni < 4; ni++) {
            int row0 = bm + wm + mi * 16 + g;
            int col  = bn + wn + ni * 8 + 2 * t;
            *(float2*)(C + (size_t)row0 * ldc + col) = make_float2(acc[mi][ni][0], acc[mi][ni][1]);
            *(float2*)(C + (size_t)(row0 + 8) * ldc + col) = make_float2(acc[mi][ni][2], acc[mi][ni][3]);
        }
    }
}

// ---------------- merged pack/convert: Wcat (n-major), WoT (n-major), uT ----------------
constexpr int PK_W   = cNP * cD;               // 4718592
constexpr int PK_WO  = cD * cVD;               // 1572864
constexpr int PK_U4  = cM * cD / 4;            // 2097152
constexpr int PK_TOT = PK_W + PK_WO + PK_U4;
__global__ void pack_all_kernel(const float* __restrict__ Wq, const float* __restrict__ Wk,
                                const float* __restrict__ Wv, const float* __restrict__ Wg,
                                const float* __restrict__ Wo, const float4* __restrict__ u4)
{
    int idx = blockIdx.x * blockDim.x + threadIdx.x;
    if (idx < PK_W) {
        int n = idx / cD, k = idx % cD;
        float v;
        if (n < cKD)                 v = Wq[k * cKD + n];
        else if (n < 2 * cKD)        v = Wk[k * cKD + (n - cKD)];
        else if (n < 2 * cKD + cVD)  v = Wv[k * cVD + (n - 2 * cKD)];
        else                         v = Wg[k * cVD + (n - 2 * cKD - cVD)];
        g_Wcat[idx] = f2tf32(v);
    } else if (idx < PK_W + PK_WO) {
        int i = idx - PK_W;
        int n = i / cVD, k = i % cVD;
        g_WoT[i] = f2tf32(Wo[k * cD + n]);
    } else if (idx < PK_TOT) {
        int i = idx - PK_W - PK_WO;
        float4 v = u4[i];
        uint4 r;
        r.x = f2tf32(v.x); r.y = f2tf32(v.y); r.z = f2tf32(v.z); r.w = f2tf32(v.w);
        ((uint4*)g_uT)[i] = r;
    }
}

// ---------------- gk / beta projections: warp per token, W in smem ----------------
__global__ void proj_gates_kernel(const float* __restrict__ u, const float* __restrict__ Wgk,
                                  const float* __restrict__ Wb, const float* __restrict__ b_b,
                                  const float* __restrict__ A_log, const float* __restrict__ dt_bias)
{
    extern __shared__ float sW[];   // [1024][16]
    const int tid = threadIdx.x;
    const int wid = tid >> 5;
    const int lane = tid & 31;

    for (int idx = tid; idx < cD * 16; idx += 256) {
        int i = idx >> 4, c = idx & 15;
        sW[idx] = (c < 8) ? Wgk[i * cH + c] : Wb[i * cH + (c - 8)];
    }
    __syncthreads();

    int m = blockIdx.x * 8 + wid;
    const float* ur = u + (size_t)m * cD;
    float s[16];
#pragma unroll
    for (int c = 0; c < 16; c++) s[c] = 0.f;
    for (int j = 0; j < 32; j++) {
        int i = lane + 32 * j;
        float uv = __ldg(ur + i);
        const float* wr = sW + i * 16;
#pragma unroll
        for (int c = 0; c < 16; c++) s[c] += uv * wr[c];
    }
#pragma unroll
    for (int c = 0; c < 16; c++) {
#pragma unroll
        for (int o = 16; o; o >>= 1) s[c] += __shfl_xor_sync(0xffffffffu, s[c], o);
    }
    if (lane < 8) {
        int h = lane;
        float x  = s[h] + dt_bias[h];
        float sp = (x > 20.f) ? x : log1pf(expf(x));
        float gkv = -expf(A_log[h]) * sp;
        int b = m / cL, l = m % cL;
        g_gk[((size_t)(b * cH + h)) * cL + l] = gkv;
    } else {
        int h = lane - 8;
        float bv = 1.f / (1.f + expf(-(s[8 + h] + b_b[h])));
        int b = m / cL, l = m % cL;
        g_bt[((size_t)(b * cH + h)) * cL + l] = bv;
    }
}

// ---------------- fused conv + SiLU + L2norm for q,k; writes head layout ----------------
__global__ void conv_qk_norm_kernel(const float* __restrict__ wq, const float* __restrict__ wk)
{
    int gw = (blockIdx.x * blockDim.x + threadIdx.x) >> 5;
    int lane = threadIdx.x & 31;
    if (gw >= cM * cH) return;
    int m = gw / cH, h = gw % cH;
    int b = m / cL, l = m % cL;
    const size_t rowbase = (size_t)(m - l) * cNP;

    float qv[3], kv[3];
    float ssq = 0.f, ssk = 0.f;
#pragma unroll
    for (int r = 0; r < 3; r++) {
        int c = h * cDK + lane + 32 * r;
        float aq = 0.f, ak = 0.f;
#pragma unroll
        for (int j = 0; j < 4; j++) {
            int ll = l - 3 + j;
            if (ll >= 0) {
                const float* rowp = g_proj + rowbase + (size_t)ll * cNP;
                aq += rowp[c]       * wq[c * 4 + j];
                ak += rowp[cKD + c] * wk[c * 4 + j];
            }
        }
        aq = aq / (1.f + expf(-aq));
        ak = ak / (1.f + expf(-ak));
        qv[r] = aq; kv[r] = ak;
        ssq += aq * aq; ssk += ak * ak;
    }
#pragma unroll
    for (int o = 16; o; o >>= 1) {
        ssq += __shfl_xor_sync(0xffffffffu, ssq, o);
        ssk += __shfl_xor_sync(0xffffffffu, ssk, o);
    }
    float iq = 1.f / fmaxf(sqrtf(ssq), 1e-12f);
    float ik = 1.f / fmaxf(sqrtf(ssk), 1e-12f);
    float* dq = g_qn + ((size_t)(b * cH + h) * cL + l) * cDK;
    float* dk = g_kn + ((size_t)(b * cH + h) * cL + l) * cDK;
#pragma unroll
    for (int r = 0; r < 3; r++) {
        dq[lane + 32 * r] = qv[r] * iq;
        dk[lane + 32 * r] = kv[r] * ik;
    }
}

// ---------------- conv + SiLU for v; writes head layout directly ----------------
__global__ void conv_v_kernel(const float* __restrict__ wv)
{
    int idx = blockIdx.x * blockDim.x + threadIdx.x;
    if (idx >= cM * cVD) return;
    int c = idx % cVD;
    int m = idx / cVD;
    int l = m % cL, b = m / cL;
    float acc = 0.f;
#pragma unroll
    for (int j = 0; j < 4; j++) {
        int ll = l - 3 + j;
        if (ll >= 0) acc += g_proj[(size_t)(m - l + ll) * cNP + 2 * cKD + c] * wv[c * 4 + j];
    }
    int h = c / cDV, d = c % cDV;
    g_vh[((size_t)(b * cH + h) * cL + l) * cDV + d] = acc / (1.f + expf(-acc));
}

// ---------------- per-chunk precompute (R10: sk padded stride 100; interleaved outputs) ----------------
constexpr int cSKS = 100;
constexpr int CP_SMEM_FLOATS = 6144 + 64 * cSKS + 6144 + 4096 + 4096 + 12288 + 64 + 64;
constexpr int CP_THREADS = 320;
__global__ void chunk_pre_kernel()
{
    extern __shared__ float sm[];
    float* sq   = sm;                    // 64 x 96
    float* sk   = sq + 6144;             // 64 x 100 (padded)
    float* skb  = sk + 64 * cSKS;        // 64 x 96
    float* sKK  = skb + 6144;            // 64 x 64
    float* sM   = sKK + 4096;            // 64 x 64
    float* sv   = sM + 4096;             // 64 x 192
    float* sdec = sv + 12288;
    float* sbet = sdec + 64;

    const int tid = threadIdx.x;
    const int cid = blockIdx.x;
    const int bh = cid / cNC;
    const int n  = cid % cNC;
    const size_t cbg  = (size_t)bh * cL + n * cCS;
    const size_t cb96  = cbg * cDK;
    const size_t cb192 = cbg * cDV;
    const float scale = rsqrtf((float)cDK);

    for (int i4 = tid; i4 < 1536; i4 += CP_THREADS) {
        ((float4*)sq)[i4] = ((const float4*)(g_qn + cb96))[i4];
        int c = i4 / 24, d4 = i4 % 24;
        ((float4*)sk)[c * (cSKS / 4) + d4] = ((const float4*)(g_kn + cb96))[i4];
    }
    if (tid < 64) sbet[tid] = g_bt[cbg + tid];
    if (tid < 32) {
        float x0 = g_gk[cbg + tid], x1 = g_gk[cbg + 32 + tid];
#pragma unroll
        for (int o = 1; o < 32; o <<= 1) {
            float y = __shfl_up_sync(0xffffffffu, x0, o);
            if (tid >= o) x0 += y;
        }
        float t0 = __shfl_sync(0xffffffffu, x0, 31);
#pragma unroll
        for (int o = 1; o < 32; o <<= 1) {
            float y = __shfl_up_sync(0xffffffffu, x1, o);
            if (tid >= o) x1 += y;
        }
        sdec[tid] = x0;
        sdec[32 + tid] = x1 + t0;
    }
    __syncthreads();
    const float dl = sdec[63];

    for (int i = tid; i < 6144; i += CP_THREADS) {
        int c = i / cDK, d = i - c * cDK;
        skb[i] = sk[c * cSKS + d] * sbet[c];
    }
    for (int i = tid; i < 12288; i += CP_THREADS) sv[i]  = g_vh[cb192 + i] * sbet[i / cDV];

    // qe: ROW-PAIR INTERLEAVED [(c>>1)][d][c&1]; kd: row-major
    for (int i = tid; i < 6144; i += CP_THREADS) {
        int c = i / cDK, d = i - c * cDK;
        g_qn[cb96 + (size_t)(c >> 1) * 192 + 2 * d + (c & 1)] = sq[i] * scale * expf(sdec[c]);
        g_kn[cb96 + i] = sk[c * cSKS + d] * expf(dl - sdec[c]);
    }
    __syncthreads();

    for (int idx = tid; idx < 4096; idx += CP_THREADS) {
        int i = idx >> 6, j = idx & 63;
        float s = 0.f;
        const float4* a4 = (const float4*)(skb + i * cDK);
        const float4* b4 = (const float4*)(sk + j * cSKS);
#pragma unroll 6
        for (int d = 0; d < cDK / 4; d++) {
            float4 a = a4[d], b = b4[d];
            s += a.x * b.x + a.y * b.y + a.z * b.z + a.w * b.w;
        }
        sKK[idx] = s;
    }
    // intra-chunk attn -> ROW-PAIR INTERLEAVED
    for (int idx = tid; idx < 4096; idx += CP_THREADS) {
        int i = idx >> 6, j = idx & 63;
        float a = 0.f;
        if (i >= j) {
            float s = 0.f;
            const float4* a4 = (const float4*)(sq + i * cDK);
            const float4* b4 = (const float4*)(sk + j * cSKS);
#pragma unroll 6
            for (int d = 0; d < cDK / 4; d++) {
                float4 x = a4[d], y = b4[d];
                s += x.x * y.x + x.y * y.y + x.z * y.z + x.w * y.w;
            }
            a = s * scale * expf(sdec[i] - sdec[j]);
        }
        g_at[(size_t)cid * 4096 + (size_t)(i >> 1) * 128 + 2 * j + (i & 1)] = a;
    }
    for (int idx = tid; idx < 4096; idx += CP_THREADS) {
        int i = idx >> 6, j = idx & 63;
        sM[idx] = (i > j) ? sKK[idx] * expf(sdec[i] - sdec[j]) : 0.f;
    }
    __syncthreads();

    for (int i = 1; i < 64; i++) {
        if (tid < 192) {
            float s = 0.f;
            const float* mrow = sM + i * 64;
            int j = 0;
            for (; j + 4 <= i; j += 4) {
                float4 m4 = *(const float4*)(mrow + j);
                s += m4.x * sv[(j + 0) * 192 + tid] + m4.y * sv[(j + 1) * 192 + tid]
                   + m4.z * sv[(j + 2) * 192 + tid] + m4.w * sv[(j + 3) * 192 + tid];
            }
            for (; j < i; j++) s += mrow[j] * sv[j * 192 + tid];
            sv[i * 192 + tid] -= s;
        } else if (tid < 288) {
            int c = tid - 192;
            float s = 0.f;
            const float* krow = sKK + i * 64;
            int j = 0;
            for (; j + 4 <= i; j += 4) {
                float4 m4 = *(const float4*)(krow + j);
                s += m4.x * skb[(j + 0) * 96 + c] + m4.y * skb[(j + 1) * 96 + c]
                   + m4.z * skb[(j + 2) * 96 + c] + m4.w * skb[(j + 3) * 96 + c];
            }
            for (; j < i; j++) s += krow[j] * skb[j * 96 + c];
            skb[i * 96 + c] -= s;
        }
        __syncthreads();
    }

    for (int i = tid; i < 12288; i += CP_THREADS) g_vh[cb192 + i] = sv[i];
    // kce: ROW-PAIR INTERLEAVED
    for (int i = tid; i < 6144; i += CP_THREADS) {
        int c = i / cDK, d = i - c * cDK;
        g_kce[cb96 + (size_t)(c >> 1) * 192 + 2 * d + (c & 1)] = skb[i] * expf(sdec[c]);
    }
    if (tid == 0) g_edl[cid] = expf(dl);
}

// ---------------- sequential scan: R10 (smem-staged + f32x2, validated) ----------------
constexpr int SC_SMEM_FLOATS = 3 * 6144 + 4096 + 2048 + 3072;
constexpr int SC_THREADS = 512;
__global__ void __launch_bounds__(SC_THREADS, 1)
scan_kernel()
{
    extern __shared__ float sm[];
    float* sqe  = sm;              // interleaved [rp][192]
    float* skce = sqe + 6144;      // interleaved [rp][192]
    float* skd  = skce + 6144;     // row-major   [c][96]
    float* sat  = skd + 6144;      // interleaved [rp][128]
    float* svn  = sat + 4096;      // [c][32]
    float* S    = svn + 2048;      // [d][32]

    const int tid = threadIdx.x;
    const int bh = blockIdx.y;
    const int e0 = blockIdx.x * 32;
    const int e  = tid & 31;
    const int w  = tid >> 5;        // 0..15
    const int c0 = w * 4;
    const int rp0 = w * 2;
    const int d0 = w * 6;

    for (int i = tid; i < 3072; i += SC_THREADS) S[i] = 0.f;

    for (int n = 0; n < cNC; n++) {
        const size_t cbg = (size_t)bh * cL + n * cCS;
        const size_t cb96 = cbg * cDK;
        const size_t cb192 = cbg * cDV;
        __syncthreads();
        for (int i = tid; i < 1536; i += SC_THREADS) {
            ((float4*)sqe)[i]  = ((const float4*)(g_qn + cb96))[i];
            ((float4*)skce)[i] = ((const float4*)(g_kce + cb96))[i];
            ((float4*)skd)[i]  = ((const float4*)(g_kn + cb96))[i];
        }
        for (int i = tid; i < 1024; i += SC_THREADS)
            ((float4*)sat)[i] = ((const float4*)(g_at + (size_t)(bh * cNC + n) * 4096))[i];
        __syncthreads();

        // ---- phase A: accv = kce@S, acco = qe@S ----
        ull accv0 = 0, accv1 = 0, acco0 = 0, acco1 = 0;
        const ulonglong2* q0 = (const ulonglong2*)(sqe + rp0 * 192);
        const ulonglong2* q1 = (const ulonglong2*)(sqe + (rp0 + 1) * 192);
        const ulonglong2* k0p = (const ulonglong2*)(skce + rp0 * 192);
        const ulonglong2* k1p = (const ulonglong2*)(skce + (rp0 + 1) * 192);
#pragma unroll 6
        for (int jg = 0; jg < 24; jg++) {
            const int j = jg * 4;
            ull b0 = pk2(S[(j + 0) * 32 + e]);
            ull b1 = pk2(S[(j + 1) * 32 + e]);
            ull b2 = pk2(S[(j + 2) * 32 + e]);
            ull b3 = pk2(S[(j + 3) * 32 + e]);
            ulonglong2 qa = q0[2 * jg], qb = q0[2 * jg + 1];
            ulonglong2 ra = q1[2 * jg], rb = q1[2 * jg + 1];
            ulonglong2 ca = k0p[2 * jg], cbv = k0p[2 * jg + 1];
            ulonglong2 da = k1p[2 * jg], db = k1p[2 * jg + 1];
            fma2(acco0, qa.x, b0); fma2(acco0, qa.y, b1); fma2(acco0, qb.x, b2); fma2(acco0, qb.y, b3);
            fma2(acco1, ra.x, b0); fma2(acco1, ra.y, b1); fma2(acco1, rb.x, b2); fma2(acco1, rb.y, b3);
            fma2(accv0, ca.x, b0); fma2(accv0, ca.y, b1); fma2(accv0, cbv.x, b2); fma2(accv0, cbv.y, b3);
            fma2(accv1, da.x, b0); fma2(accv1, da.y, b1); fma2(accv1, db.x, b2); fma2(accv1, db.y, b3);
        }
        {
            float su0 = __ldg(g_vh + cb192 + (size_t)(c0 + 0) * cDV + e0 + e);
            float su1 = __ldg(g_vh + cb192 + (size_t)(c0 + 1) * cDV + e0 + e);
            float su2 = __ldg(g_vh + cb192 + (size_t)(c0 + 2) * cDV + e0 + e);
            float su3 = __ldg(g_vh + cb192 + (size_t)(c0 + 3) * cDV + e0 + e);
            float2 v01 = upk2(accv0);
            float2 v23 = upk2(accv1);
            svn[(c0 + 0) * 32 + e] = su0 - v01.x;
            svn[(c0 + 1) * 32 + e] = su1 - v01.y;
            svn[(c0 + 2) * 32 + e] = su2 - v23.x;
            svn[(c0 + 3) * 32 + e] = su3 - v23.y;
        }
        __syncthreads();

        // ---- phase B: o += attn@v_new ; accS = kd^T@v_new ----
        const float el = __ldg(g_edl + bh * cNC + n);
        ull accS0 = 0, accS1 = 0, accS2 = 0;
        const ulonglong2* a0 = (const ulonglong2*)(sat + rp0 * 128);
        const ulonglong2* a1 = (const ulonglong2*)(sat + (rp0 + 1) * 128);
#pragma unroll 8
        for (int c = 0; c < 64; c += 2) {
            ull bva = pk2(svn[c * 32 + e]);
            ull bvb = pk2(svn[(c + 1) * 32 + e]);
            ulonglong2 v0 = a0[c >> 1];
            ulonglong2 v1 = a1[c >> 1];
            fma2(acco0, v0.x, bva); fma2(acco0, v0.y, bvb);
            fma2(acco1, v1.x, bva); fma2(acco1, v1.y, bvb);
            const ull* kr0 = (const ull*)(skd + (size_t)c * cDK + d0);
            const ull* kr1 = (const ull*)(skd + (size_t)(c + 1) * cDK + d0);
            fma2(accS0, kr0[0], bva); fma2(accS1, kr0[1], bva); fma2(accS2, kr0[2], bva);
            fma2(accS0, kr1[0], bvb); fma2(accS1, kr1[1], bvb); fma2(accS2, kr1[2], bvb);
        }
        {
            float2 o01 = upk2(acco0);
            float2 o23 = upk2(acco1);
            g_o[cb192 + (size_t)(c0 + 0) * cDV + e0 + e] = o01.x;
            g_o[cb192 + (size_t)(c0 + 1) * cDV + e0 + e] = o01.y;
            g_o[cb192 + (size_t)(c0 + 2) * cDV + e0 + e] = o23.x;
            g_o[cb192 + (size_t)(c0 + 3) * cDV + e0 + e] = o23.y;
        }
        {
            float2 s01 = upk2(accS0);
            float2 s23 = upk2(accS1);
            float2 s45 = upk2(accS2);
            int i0 = d0 * 32 + e;
            S[i0]       = S[i0] * el + s01.x;
            S[i0 + 32]  = S[i0 + 32] * el + s01.y;
            S[i0 + 64]  = S[i0 + 64] * el + s23.x;
            S[i0 + 96]  = S[i0 + 96] * el + s23.y;
            S[i0 + 128] = S[i0 + 128] * el + s45.x;
            S[i0 + 160] = S[i0 + 160] * el + s45.y;
        }
    }
}

// ---------------- gated RMS norm + transpose back (writes tf32 bits) ----------------
__global__ void gate_norm_kernel(const float* __restrict__ norm_w)
{
    int gw = (blockIdx.x * blockDim.x + threadIdx.x) >> 5;
    int lane = threadIdx.x & 31;
    if (gw >= cM * cH) return;
    int m = gw / cH, h = gw % cH;
    int b = m / cL, l = m % cL;
    const float* orow = g_o + ((size_t)(b * cH + h) * cL + l) * cDV;
    float vals[6];
    float ss = 0.f;
#pragma unroll
    for (int k = 0; k < 6; k++) {
        float v = orow[lane + 32 * k];
        vals[k] = v;
        ss += v * v;
    }
#pragma unroll
    for (int o = 16; o; o >>= 1) ss += __shfl_xor_sync(0xffffffffu, ss, o);
    float r = 1.f / sqrtf(ss / (float)cDV + 1e-5f);
#pragma unroll
    for (int k = 0; k < 6; k++) {
        int d = lane + 32 * k;
        float gg = g_proj[(size_t)m * cNP + 2 * cKD + cVD + h * cDV + d];
        float sg = gg / (1.f + expf(-gg));
        g_on[(size_t)m * cVD + h * cDV + d] = f2tf32(vals[k] * r * norm_w[d] * sg);
    }
}

// ---------------- host launch ----------------
template <typename T>
static T* sym(const void* symbol)
{
    void* p = nullptr;
    cudaGetSymbolAddress(&p, symbol);
    return (T*)p;
}

extern "C" void kernel_launch(void* const* d_in, const int* in_sizes, int n_in,
                              void* d_out, int out_size)
{
    const float* u       = (const float*)d_in[0];
    const float* Wq      = (const float*)d_in[1];
    const float* Wk      = (const float*)d_in[2];
    const float* Wv      = (const float*)d_in[3];
    const float* Wg      = (const float*)d_in[4];
    const float* Wo      = (const float*)d_in[5];
    const float* Wgk     = (const float*)d_in[6];
    const float* Wb      = (const float*)d_in[7];
    const float* b_b     = (const float*)d_in[8];
    const float* A_log   = (const float*)d_in[9];
    const float* dt_bias = (const float*)d_in[10];
    const float* conv_q  = (const float*)d_in[11];
    const float* conv_k  = (const float*)d_in[12];
    const float* conv_v  = (const float*)d_in[13];
    const float* norm_w  = (const float*)d_in[14];
    float* out = (float*)d_out;

    uint32_t* Wcat = sym<uint32_t>(g_Wcat);
    uint32_t* WoT  = sym<uint32_t>(g_WoT);
    uint32_t* uT   = sym<uint32_t>(g_uT);
    uint32_t* on   = sym<uint32_t>(g_on);
    float* proj = sym<float>(g_proj);

    cudaFuncSetAttribute(gemm_tf32_kernel, cudaFuncAttributeMaxDynamicSharedMemorySize, GEMM_SMEM);
    cudaFuncSetAttribute(chunk_pre_kernel, cudaFuncAttributeMaxDynamicSharedMemorySize,
                         CP_SMEM_FLOATS * (int)sizeof(float));
    cudaFuncSetAttribute(scan_kernel, cudaFuncAttributeMaxDynamicSharedMemorySize,
                         SC_SMEM_FLOATS * (int)sizeof(float));
    cudaFuncSetAttribute(proj_gates_kernel, cudaFuncAttributeMaxDynamicSharedMemorySize, 65536);

    // merged pack/convert (Wcat n-major | WoT n-major | u tf32)
    pack_all_kernel<<<(PK_TOT + 255) / 256, 256>>>(Wq, Wk, Wv, Wg, Wo, (const float4*)u);

    // fused projection GEMM (q|k|v|g)
    gemm_tf32_kernel<<<dim3(cNP / 128, cM / 128), 256, GEMM_SMEM>>>(
        uT, cD, Wcat, cD, proj, cNP, cM, cNP, cD);

    // gates
    proj_gates_kernel<<<cM / 8, 256, 65536>>>(u, Wgk, Wb, b_b, A_log, dt_bias);

    // fused conv+silu(+l2norm) -> head layouts
    conv_qk_norm_kernel<<<(cM * cH * 32 + 255) / 256, 256>>>(conv_q, conv_k);
    conv_v_kernel<<<(cM * cVD + 255) / 256, 256>>>(conv_v);

    // delta-rule chunk precompute + scan
    chunk_pre_kernel<<<cBH * cNC, CP_THREADS, CP_SMEM_FLOATS * sizeof(float)>>>();
    scan_kernel<<<dim3(6, cBH), SC_THREADS, SC_SMEM_FLOATS * sizeof(float)>>>();

    // gated rms norm + output projection
    gate_norm_kernel<<<(cM * cH * 32 + 255) / 256, 256>>>(norm_w);
    gemm_tf32_kernel<<<dim3(cD / 128, cM / 128), 256, GEMM_SMEM>>>(
        on, cVD, WoT, cVD, out, cD, cM, cD, cVD);
}

// round 17
// speedup vs baseline: 1.3372x; 1.0641x over previous
#include <cuda_runtime.h>
#include <math.h>
#include <stdint.h>

// ---------------- problem constants ----------------
constexpr int cB  = 2;
constexpr int cL  = 4096;
constexpr int cD  = 1024;   // D_MODEL
constexpr int cKD = 768;    // KEY_DIM
constexpr int cVD = 1536;   // VALUE_DIM
constexpr int cH  = 8;
constexpr int cDK = 96;     // per-head qk dim
constexpr int cDV = 192;    // per-head v dim
constexpr int cCS = 64;     // chunk size
constexpr int cNC = cL / cCS;       // 64 chunks per sequence
constexpr int cM  = cB * cL;        // 8192 tokens
constexpr int cBH = cB * cH;        // 16
constexpr int cNP = cKD + cKD + cVD + cVD;  // 4608 packed projection width

typedef unsigned long long ull;

// ---------------- scratch (device globals; no cudaMalloc allowed) ----------------
__device__ uint32_t g_Wcat[cNP * cD];   // [Wq|Wk|Wv|Wg] TRANSPOSED (n-major), tf32 bits
__device__ uint32_t g_WoT [cD * cVD];   // Wo TRANSPOSED (n-major), tf32 bits
__device__ uint32_t g_uT  [cM * cD];    // u, tf32 bits
__device__ float g_proj[cM * cNP];      // packed projection outputs (fp32)
__device__ float g_qn [cM * cKD];   // qn; becomes qe (ROW-PAIR INTERLEAVED) after chunk_pre
__device__ float g_kn [cM * cKD];   // kn; becomes kd (row-major) after chunk_pre
__device__ float g_vh [cM * cVD];   // head layout; becomes u_ after chunk_pre
__device__ float g_kce[cM * cKD];   // kcd * exp(dec), ROW-PAIR INTERLEAVED
__device__ float g_gk [cBH * cL];
__device__ float g_bt [cBH * cL];
__device__ float g_at [cBH * cNC * cCS * cCS];  // intra-chunk attn, ROW-PAIR INTERLEAVED
__device__ float g_edl[cBH * cNC];
__device__ float g_o  [cM * cVD];   // (b,h,l,dv)
__device__ uint32_t g_on [cM * cVD];   // gated+normed, tf32 bits

// ---------------- tf32 / f32x2 helpers ----------------
__device__ __forceinline__ uint32_t f2tf32(float f)
{
    uint32_t r;
    asm("cvt.rna.tf32.f32 %0, %1;" : "=r"(r) : "f"(f));
    return r;
}

__device__ __forceinline__ void mma_tf32(float c[4], const uint32_t a[4], const uint32_t b[2])
{
    asm volatile(
        "mma.sync.aligned.m16n8k8.row.col.f32.tf32.tf32.f32 "
        "{%0,%1,%2,%3}, {%4,%5,%6,%7}, {%8,%9}, {%0,%1,%2,%3};"
        : "+f"(c[0]), "+f"(c[1]), "+f"(c[2]), "+f"(c[3])
        : "r"(a[0]), "r"(a[1]), "r"(a[2]), "r"(a[3]), "r"(b[0]), "r"(b[1]));
}

__device__ __forceinline__ ull pk2(float x)
{
    ull r;
    asm("mov.b64 %0, {%1,%1};" : "=l"(r) : "f"(x));
    return r;
}

__device__ __forceinline__ void fma2(ull& d, ull a, ull b)
{
    asm("fma.rn.f32x2 %0, %1, %2, %3;" : "=l"(d) : "l"(a), "l"(b), "l"(d));
}

__device__ __forceinline__ float2 upk2(ull v)
{
    float2 r;
    asm("mov.b64 {%0,%1}, %2;" : "=f"(r.x), "=f"(r.y) : "l"(v));
    return r;
}

#define CP16(dst, src) \
    asm volatile("cp.async.cg.shared.global [%0], [%1], 16;" :: "r"(dst), "l"(src))

#define LDSM4(r0, r1, r2, r3, addr) \
    asm volatile("ldmatrix.sync.aligned.m8n8.x4.shared.b16 {%0,%1,%2,%3}, [%4];" \
                 : "=r"(r0), "=r"(r1), "=r"(r2), "=r"(r3) : "r"(addr))

// ---------------- tf32 tensor-core GEMM (R10: 4-stage, 2 CTAs/SM, k16, ROWW 20) ----------------
constexpr int GEMM_STAGES = 4;
constexpr int GEMM_STAGE_WORDS = 128 * 20;
constexpr int GEMM_SMEM = GEMM_STAGES * 2 * GEMM_STAGE_WORDS * 4;
__global__ void __launch_bounds__(256, 2)
gemm_tf32_kernel(const uint32_t* __restrict__ A, int lda,
                 const uint32_t* __restrict__ B, int ldb,
                 float* __restrict__ C, int ldc,
                 int M, int N, int K)
{
    extern __shared__ uint32_t smem_u[];
    uint32_t* As = smem_u;
    uint32_t* Bs = smem_u + GEMM_STAGES * GEMM_STAGE_WORDS;

    const int tid  = threadIdx.x;
    const int wid  = tid >> 5;
    const int lane = tid & 31;
    const int g    = lane >> 2;
    const int t    = lane & 3;
    const int wm   = (wid >> 2) * 64;
    const int wn   = (wid & 3) * 32;

    const int bm = blockIdx.y * 128;
    const int bn = blockIdx.x * 128;

    const int row = tid >> 1;
    const int cb  = (tid & 1) * 8;
    const uint32_t* Ag = A + (size_t)(bm + row) * lda + cb;
    const uint32_t* Bg = B + (size_t)(bn + row) * ldb + cb;

    const uint32_t sA0 = (uint32_t)__cvta_generic_to_shared(As + row * 20 + cb);
    const uint32_t sB0 = (uint32_t)__cvta_generic_to_shared(Bs + row * 20 + cb);
    constexpr uint32_t STG_B = GEMM_STAGE_WORDS * 4;

    const int rA = wm + ((lane >> 3) & 1) * 8 + (lane & 7);
    const int cA = (lane >> 4) * 4;
    const int rB = wn + (lane >> 4) * 8 + (lane & 7);
    const int cB2 = ((lane >> 3) & 1) * 4;
    const uint32_t lA0 = (uint32_t)__cvta_generic_to_shared(As + rA * 20 + cA);
    const uint32_t lB0 = (uint32_t)__cvta_generic_to_shared(Bs + rB * 20 + cB2);

    float acc[4][4][4];
#pragma unroll
    for (int i = 0; i < 4; i++)
#pragma unroll
        for (int j = 0; j < 4; j++)
#pragma unroll
            for (int r = 0; r < 4; r++) acc[i][j][r] = 0.f;

    const int nt = K >> 4;

#pragma unroll
    for (int s = 0; s < GEMM_STAGES - 1; s++) {
        const uint32_t* a = Ag + (size_t)s * 16;
        const uint32_t* b = Bg + (size_t)s * 16;
        CP16(sA0 + s * STG_B, a); CP16(sA0 + s * STG_B + 16, a + 4);
        CP16(sB0 + s * STG_B, b); CP16(sB0 + s * STG_B + 16, b + 4);
        asm volatile("cp.async.commit_group;");
    }

    for (int kt = 0; kt < nt; kt++) {
        asm volatile("cp.async.wait_group 2;");
        __syncthreads();

        const int buf = kt & (GEMM_STAGES - 1);
        const uint32_t offA = lA0 + buf * STG_B;
        const uint32_t offB = lB0 + buf * STG_B;
#pragma unroll
        for (int ks = 0; ks < 16; ks += 8) {
            uint32_t af[4][4], bf[4][2];
#pragma unroll
            for (int mi = 0; mi < 4; mi++)
                LDSM4(af[mi][0], af[mi][1], af[mi][2], af[mi][3],
                      offA + mi * (16 * 20 * 4) + ks * 4);
#pragma unroll
            for (int np = 0; np < 2; np++)
                LDSM4(bf[2 * np][0], bf[2 * np][1], bf[2 * np + 1][0], bf[2 * np + 1][1],
                      offB + np * (16 * 20 * 4) + ks * 4);
#pragma unroll
            for (int mi = 0; mi < 4; mi++)
#pragma unroll
                for (int ni = 0; ni < 4; ni++)
                    mma_tf32(acc[mi][ni], af[mi], bf[ni]);
        }

        if (kt + GEMM_STAGES - 1 < nt) {
            const int s = (kt + GEMM_STAGES - 1) & (GEMM_STAGES - 1);
            const uint32_t* a = Ag + (size_t)(kt + GEMM_STAGES - 1) * 16;
            const uint32_t* b = Bg + (size_t)(kt + GEMM_STAGES - 1) * 16;
            CP16(sA0 + s * STG_B, a); CP16(sA0 + s * STG_B + 16, a + 4);
            CP16(sB0 + s * STG_B, b); CP16(sB0 + s * STG_B + 16, b + 4);
        }
        asm volatile("cp.async.commit_group;");
    }

#pragma unroll
    for (int mi = 0; mi < 4; mi++) {
#pragma unroll
        for (int ni = 0; ni < 4; ni++) {
            int row0 = bm + wm + mi * 16 + g;
            int col  = bn + wn + ni * 8 + 2 * t;
            *(float2*)(C + (size_t)row0 * ldc + col) = make_float2(acc[mi][ni][0], acc[mi][ni][1]);
            *(float2*)(C + (size_t)(row0 + 8) * ldc + col) = make_float2(acc[mi][ni][2], acc[mi][ni][3]);
        }
    }
}

// ---------------- merged pack/convert: Wcat (n-major), WoT (n-major), uT ----------------
constexpr int PK_W   = cNP * cD;
constexpr int PK_WO  = cD * cVD;
constexpr int PK_U4  = cM * cD / 4;
constexpr int PK_TOT = PK_W + PK_WO + PK_U4;
__global__ void pack_all_kernel(const float* __restrict__ Wq, const float* __restrict__ Wk,
                                const float* __restrict__ Wv, const float* __restrict__ Wg,
                                const float* __restrict__ Wo, const float4* __restrict__ u4)
{
    int idx = blockIdx.x * blockDim.x + threadIdx.x;
    if (idx < PK_W) {
        int n = idx / cD, k = idx % cD;
        float v;
        if (n < cKD)                 v = Wq[k * cKD + n];
        else if (n < 2 * cKD)        v = Wk[k * cKD + (n - cKD)];
        else if (n < 2 * cKD + cVD)  v = Wv[k * cVD + (n - 2 * cKD)];
        else                         v = Wg[k * cVD + (n - 2 * cKD - cVD)];
        g_Wcat[idx] = f2tf32(v);
    } else if (idx < PK_W + PK_WO) {
        int i = idx - PK_W;
        int n = i / cVD, k = i % cVD;
        g_WoT[i] = f2tf32(Wo[k * cD + n]);
    } else if (idx < PK_TOT) {
        int i = idx - PK_W - PK_WO;
        float4 v = u4[i];
        uint4 r;
        r.x = f2tf32(v.x); r.y = f2tf32(v.y); r.z = f2tf32(v.z); r.w = f2tf32(v.w);
        ((uint4*)g_uT)[i] = r;
    }
}

// ---------------- gk / beta projections: warp per token, W in smem ----------------
__global__ void proj_gates_kernel(const float* __restrict__ u, const float* __restrict__ Wgk,
                                  const float* __restrict__ Wb, const float* __restrict__ b_b,
                                  const float* __restrict__ A_log, const float* __restrict__ dt_bias)
{
    extern __shared__ float sW[];   // [1024][16]
    const int tid = threadIdx.x;
    const int wid = tid >> 5;
    const int lane = tid & 31;

    for (int idx = tid; idx < cD * 16; idx += 256) {
        int i = idx >> 4, c = idx & 15;
        sW[idx] = (c < 8) ? Wgk[i * cH + c] : Wb[i * cH + (c - 8)];
    }
    __syncthreads();

    int m = blockIdx.x * 8 + wid;
    const float* ur = u + (size_t)m * cD;
    float s[16];
#pragma unroll
    for (int c = 0; c < 16; c++) s[c] = 0.f;
    for (int j = 0; j < 32; j++) {
        int i = lane + 32 * j;
        float uv = __ldg(ur + i);
        const float* wr = sW + i * 16;
#pragma unroll
        for (int c = 0; c < 16; c++) s[c] += uv * wr[c];
    }
#pragma unroll
    for (int c = 0; c < 16; c++) {
#pragma unroll
        for (int o = 16; o; o >>= 1) s[c] += __shfl_xor_sync(0xffffffffu, s[c], o);
    }
    if (lane < 8) {
        int h = lane;
        float x  = s[h] + dt_bias[h];
        float sp = (x > 20.f) ? x : log1pf(expf(x));
        float gkv = -expf(A_log[h]) * sp;
        int b = m / cL, l = m % cL;
        g_gk[((size_t)(b * cH + h)) * cL + l] = gkv;
    } else {
        int h = lane - 8;
        float bv = 1.f / (1.f + expf(-(s[8 + h] + b_b[h])));
        int b = m / cL, l = m % cL;
        g_bt[((size_t)(b * cH + h)) * cL + l] = bv;
    }
}

// ---------------- fused conv + SiLU + L2norm for q,k; writes head layout ----------------
__global__ void conv_qk_norm_kernel(const float* __restrict__ wq, const float* __restrict__ wk)
{
    int gw = (blockIdx.x * blockDim.x + threadIdx.x) >> 5;
    int lane = threadIdx.x & 31;
    if (gw >= cM * cH) return;
    int m = gw / cH, h = gw % cH;
    int b = m / cL, l = m % cL;
    const size_t rowbase = (size_t)(m - l) * cNP;

    float qv[3], kv[3];
    float ssq = 0.f, ssk = 0.f;
#pragma unroll
    for (int r = 0; r < 3; r++) {
        int c = h * cDK + lane + 32 * r;
        float aq = 0.f, ak = 0.f;
#pragma unroll
        for (int j = 0; j < 4; j++) {
            int ll = l - 3 + j;
            if (ll >= 0) {
                const float* rowp = g_proj + rowbase + (size_t)ll * cNP;
                aq += rowp[c]       * wq[c * 4 + j];
                ak += rowp[cKD + c] * wk[c * 4 + j];
            }
        }
        aq = aq / (1.f + expf(-aq));
        ak = ak / (1.f + expf(-ak));
        qv[r] = aq; kv[r] = ak;
        ssq += aq * aq; ssk += ak * ak;
    }
#pragma unroll
    for (int o = 16; o; o >>= 1) {
        ssq += __shfl_xor_sync(0xffffffffu, ssq, o);
        ssk += __shfl_xor_sync(0xffffffffu, ssk, o);
    }
    float iq = 1.f / fmaxf(sqrtf(ssq), 1e-12f);
    float ik = 1.f / fmaxf(sqrtf(ssk), 1e-12f);
    float* dq = g_qn + ((size_t)(b * cH + h) * cL + l) * cDK;
    float* dk = g_kn + ((size_t)(b * cH + h) * cL + l) * cDK;
#pragma unroll
    for (int r = 0; r < 3; r++) {
        dq[lane + 32 * r] = qv[r] * iq;
        dk[lane + 32 * r] = kv[r] * ik;
    }
}

// ---------------- conv + SiLU for v; writes head layout directly ----------------
__global__ void conv_v_kernel(const float* __restrict__ wv)
{
    int idx = blockIdx.x * blockDim.x + threadIdx.x;
    if (idx >= cM * cVD) return;
    int c = idx % cVD;
    int m = idx / cVD;
    int l = m % cL, b = m / cL;
    float acc = 0.f;
#pragma unroll
    for (int j = 0; j < 4; j++) {
        int ll = l - 3 + j;
        if (ll >= 0) acc += g_proj[(size_t)(m - l + ll) * cNP + 2 * cKD + c] * wv[c * 4 + j];
    }
    int h = c / cDV, d = c % cDV;
    g_vh[((size_t)(b * cH + h) * cL + l) * cDV + d] = acc / (1.f + expf(-acc));
}

// ---------------- per-chunk precompute: smem overlay (sv aliases sq+sk) -> 2 blocks/SM ----------------
constexpr int cSKS = 100;
// layout: sq(6144) sk(6400) skb(6144) sKK(4096) sM(4096) sdec(64) sbet(64) = 27008 floats (105.5KB)
// sv(12288) OVERLAYS sq+sk (12544) after they are dead.
constexpr int CP_SMEM_FLOATS = 6144 + 64 * cSKS + 6144 + 4096 + 4096 + 64 + 64;
constexpr int CP_THREADS = 320;
__global__ void __launch_bounds__(CP_THREADS, 2)
chunk_pre_kernel()
{
    extern __shared__ float sm[];
    float* sq   = sm;                    // 64 x 96
    float* sk   = sq + 6144;             // 64 x 100 (padded)
    float* skb  = sk + 64 * cSKS;        // 64 x 96
    float* sKK  = skb + 6144;            // 64 x 64
    float* sM   = sKK + 4096;            // 64 x 64
    float* sdec = sM + 4096;
    float* sbet = sdec + 64;
    float* sv   = sm;                    // 64 x 192, overlays sq+sk

    const int tid = threadIdx.x;
    const int cid = blockIdx.x;
    const int bh = cid / cNC;
    const int n  = cid % cNC;
    const size_t cbg  = (size_t)bh * cL + n * cCS;
    const size_t cb96  = cbg * cDK;
    const size_t cb192 = cbg * cDV;
    const float scale = rsqrtf((float)cDK);

    // --- load q,k; gates ---
    for (int i4 = tid; i4 < 1536; i4 += CP_THREADS) {
        ((float4*)sq)[i4] = ((const float4*)(g_qn + cb96))[i4];
        int c = i4 / 24, d4 = i4 % 24;
        ((float4*)sk)[c * (cSKS / 4) + d4] = ((const float4*)(g_kn + cb96))[i4];
    }
    if (tid < 64) sbet[tid] = g_bt[cbg + tid];
    if (tid < 32) {
        float x0 = g_gk[cbg + tid], x1 = g_gk[cbg + 32 + tid];
#pragma unroll
        for (int o = 1; o < 32; o <<= 1) {
            float y = __shfl_up_sync(0xffffffffu, x0, o);
            if (tid >= o) x0 += y;
        }
        float t0 = __shfl_sync(0xffffffffu, x0, 31);
#pragma unroll
        for (int o = 1; o < 32; o <<= 1) {
            float y = __shfl_up_sync(0xffffffffu, x1, o);
            if (tid >= o) x1 += y;
        }
        sdec[tid] = x0;
        sdec[32 + tid] = x1 + t0;
    }
    __syncthreads();
    const float dl = sdec[63];

    // --- skb = k*beta; write qe (interleaved) and kd ---
    for (int i = tid; i < 6144; i += CP_THREADS) {
        int c = i / cDK, d = i - c * cDK;
        float kvv = sk[c * cSKS + d];
        skb[i] = kvv * sbet[c];
        g_qn[cb96 + (size_t)(c >> 1) * 192 + 2 * d + (c & 1)] = sq[i] * scale * expf(sdec[c]);
        g_kn[cb96 + i] = kvv * expf(dl - sdec[c]);
    }
    __syncthreads();

    // --- KK = kb @ k^T ; attn -> global (interleaved) ---
    for (int idx = tid; idx < 4096; idx += CP_THREADS) {
        int i = idx >> 6, j = idx & 63;
        float s = 0.f;
        const float4* a4 = (const float4*)(skb + i * cDK);
        const float4* b4 = (const float4*)(sk + j * cSKS);
#pragma unroll 6
        for (int d = 0; d < cDK / 4; d++) {
            float4 a = a4[d], b = b4[d];
            s += a.x * b.x + a.y * b.y + a.z * b.z + a.w * b.w;
        }
        sKK[idx] = s;
    }
    for (int idx = tid; idx < 4096; idx += CP_THREADS) {
        int i = idx >> 6, j = idx & 63;
        float a = 0.f;
        if (i >= j) {
            float s = 0.f;
            const float4* a4 = (const float4*)(sq + i * cDK);
            const float4* b4 = (const float4*)(sk + j * cSKS);
#pragma unroll 6
            for (int d = 0; d < cDK / 4; d++) {
                float4 x = a4[d], y = b4[d];
                s += x.x * y.x + x.y * y.y + x.z * y.z + x.w * y.w;
            }
            a = s * scale * expf(sdec[i] - sdec[j]);
        }
        g_at[(size_t)cid * 4096 + (size_t)(i >> 1) * 128 + 2 * j + (i & 1)] = a;
    }
    __syncthreads();   // sKK ready; sq/sk now DEAD

    // --- sM = masked KK ; load sv = v*beta into overlay region ---
    for (int idx = tid; idx < 4096; idx += CP_THREADS) {
        int i = idx >> 6, j = idx & 63;
        sM[idx] = (i > j) ? sKK[idx] * expf(sdec[i] - sdec[j]) : 0.f;
    }
    for (int i = tid; i < 12288; i += CP_THREADS)
        sv[i] = g_vh[cb192 + i] * sbet[i / cDV];
    __syncthreads();

    // --- concurrent forward substitutions (identical to champion) ---
    for (int i = 1; i < 64; i++) {
        if (tid < 192) {
            float s = 0.f;
            const float* mrow = sM + i * 64;
            int j = 0;
            for (; j + 4 <= i; j += 4) {
                float4 m4 = *(const float4*)(mrow + j);
                s += m4.x * sv[(j + 0) * 192 + tid] + m4.y * sv[(j + 1) * 192 + tid]
                   + m4.z * sv[(j + 2) * 192 + tid] + m4.w * sv[(j + 3) * 192 + tid];
            }
            for (; j < i; j++) s += mrow[j] * sv[j * 192 + tid];
            sv[i * 192 + tid] -= s;
        } else if (tid < 288) {
            int c = tid - 192;
            float s = 0.f;
            const float* krow = sKK + i * 64;
            int j = 0;
            for (; j + 4 <= i; j += 4) {
                float4 m4 = *(const float4*)(krow + j);
                s += m4.x * skb[(j + 0) * 96 + c] + m4.y * skb[(j + 1) * 96 + c]
                   + m4.z * skb[(j + 2) * 96 + c] + m4.w * skb[(j + 3) * 96 + c];
            }
            for (; j < i; j++) s += krow[j] * skb[j * 96 + c];
            skb[i * 96 + c] -= s;
        }
        __syncthreads();
    }

    for (int i = tid; i < 12288; i += CP_THREADS) g_vh[cb192 + i] = sv[i];
    // kce: ROW-PAIR INTERLEAVED
    for (int i = tid; i < 6144; i += CP_THREADS) {
        int c = i / cDK, d = i - c * cDK;
        g_kce[cb96 + (size_t)(c >> 1) * 192 + 2 * d + (c & 1)] = skb[i] * expf(sdec[c]);
    }
    if (tid == 0) g_edl[cid] = expf(dl);
}

// ---------------- sequential scan: R10 (smem-staged + f32x2, validated) ----------------
constexpr int SC_SMEM_FLOATS = 3 * 6144 + 4096 + 2048 + 3072;
constexpr int SC_THREADS = 512;
__global__ void __launch_bounds__(SC_THREADS, 1)
scan_kernel()
{
    extern __shared__ float sm[];
    float* sqe  = sm;              // interleaved [rp][192]
    float* skce = sqe + 6144;      // interleaved [rp][192]
    float* skd  = skce + 6144;     // row-major   [c][96]
    float* sat  = skd + 6144;      // interleaved [rp][128]
    float* svn  = sat + 4096;      // [c][32]
    float* S    = svn + 2048;      // [d][32]

    const int tid = threadIdx.x;
    const int bh = blockIdx.y;
    const int e0 = blockIdx.x * 32;
    const int e  = tid & 31;
    const int w  = tid >> 5;        // 0..15
    const int c0 = w * 4;
    const int rp0 = w * 2;
    const int d0 = w * 6;

    for (int i = tid; i < 3072; i += SC_THREADS) S[i] = 0.f;

    for (int n = 0; n < cNC; n++) {
        const size_t cbg = (size_t)bh * cL + n * cCS;
        const size_t cb96 = cbg * cDK;
        const size_t cb192 = cbg * cDV;
        __syncthreads();
        for (int i = tid; i < 1536; i += SC_THREADS) {
            ((float4*)sqe)[i]  = ((const float4*)(g_qn + cb96))[i];
            ((float4*)skce)[i] = ((const float4*)(g_kce + cb96))[i];
            ((float4*)skd)[i]  = ((const float4*)(g_kn + cb96))[i];
        }
        for (int i = tid; i < 1024; i += SC_THREADS)
            ((float4*)sat)[i] = ((const float4*)(g_at + (size_t)(bh * cNC + n) * 4096))[i];
        __syncthreads();

        // ---- phase A: accv = kce@S, acco = qe@S ----
        ull accv0 = 0, accv1 = 0, acco0 = 0, acco1 = 0;
        const ulonglong2* q0 = (const ulonglong2*)(sqe + rp0 * 192);
        const ulonglong2* q1 = (const ulonglong2*)(sqe + (rp0 + 1) * 192);
        const ulonglong2* k0p = (const ulonglong2*)(skce + rp0 * 192);
        const ulonglong2* k1p = (const ulonglong2*)(skce + (rp0 + 1) * 192);
#pragma unroll 6
        for (int jg = 0; jg < 24; jg++) {
            const int j = jg * 4;
            ull b0 = pk2(S[(j + 0) * 32 + e]);
            ull b1 = pk2(S[(j + 1) * 32 + e]);
            ull b2 = pk2(S[(j + 2) * 32 + e]);
            ull b3 = pk2(S[(j + 3) * 32 + e]);
            ulonglong2 qa = q0[2 * jg], qb = q0[2 * jg + 1];
            ulonglong2 ra = q1[2 * jg], rb = q1[2 * jg + 1];
            ulonglong2 ca = k0p[2 * jg], cbv = k0p[2 * jg + 1];
            ulonglong2 da = k1p[2 * jg], db = k1p[2 * jg + 1];
            fma2(acco0, qa.x, b0); fma2(acco0, qa.y, b1); fma2(acco0, qb.x, b2); fma2(acco0, qb.y, b3);
            fma2(acco1, ra.x, b0); fma2(acco1, ra.y, b1); fma2(acco1, rb.x, b2); fma2(acco1, rb.y, b3);
            fma2(accv0, ca.x, b0); fma2(accv0, ca.y, b1); fma2(accv0, cbv.x, b2); fma2(accv0, cbv.y, b3);
            fma2(accv1, da.x, b0); fma2(accv1, da.y, b1); fma2(accv1, db.x, b2); fma2(accv1, db.y, b3);
        }
        {
            float su0 = __ldg(g_vh + cb192 + (size_t)(c0 + 0) * cDV + e0 + e);
            float su1 = __ldg(g_vh + cb192 + (size_t)(c0 + 1) * cDV + e0 + e);
            float su2 = __ldg(g_vh + cb192 + (size_t)(c0 + 2) * cDV + e0 + e);
            float su3 = __ldg(g_vh + cb192 + (size_t)(c0 + 3) * cDV + e0 + e);
            float2 v01 = upk2(accv0);
            float2 v23 = upk2(accv1);
            svn[(c0 + 0) * 32 + e] = su0 - v01.x;
            svn[(c0 + 1) * 32 + e] = su1 - v01.y;
            svn[(c0 + 2) * 32 + e] = su2 - v23.x;
            svn[(c0 + 3) * 32 + e] = su3 - v23.y;
        }
        __syncthreads();

        // ---- phase B: o += attn@v_new ; accS = kd^T@v_new ----
        const float el = __ldg(g_edl + bh * cNC + n);
        ull accS0 = 0, accS1 = 0, accS2 = 0;
        const ulonglong2* a0 = (const ulonglong2*)(sat + rp0 * 128);
        const ulonglong2* a1 = (const ulonglong2*)(sat + (rp0 + 1) * 128);
#pragma unroll 8
        for (int c = 0; c < 64; c += 2) {
            ull bva = pk2(svn[c * 32 + e]);
            ull bvb = pk2(svn[(c + 1) * 32 + e]);
            ulonglong2 v0 = a0[c >> 1];
            ulonglong2 v1 = a1[c >> 1];
            fma2(acco0, v0.x, bva); fma2(acco0, v0.y, bvb);
            fma2(acco1, v1.x, bva); fma2(acco1, v1.y, bvb);
            const ull* kr0 = (const ull*)(skd + (size_t)c * cDK + d0);
            const ull* kr1 = (const ull*)(skd + (size_t)(c + 1) * cDK + d0);
            fma2(accS0, kr0[0], bva); fma2(accS1, kr0[1], bva); fma2(accS2, kr0[2], bva);
            fma2(accS0, kr1[0], bvb); fma2(accS1, kr1[1], bvb); fma2(accS2, kr1[2], bvb);
        }
        {
            float2 o01 = upk2(acco0);
            float2 o23 = upk2(acco1);
            g_o[cb192 + (size_t)(c0 + 0) * cDV + e0 + e] = o01.x;
            g_o[cb192 + (size_t)(c0 + 1) * cDV + e0 + e] = o01.y;
            g_o[cb192 + (size_t)(c0 + 2) * cDV + e0 + e] = o23.x;
            g_o[cb192 + (size_t)(c0 + 3) * cDV + e0 + e] = o23.y;
        }
        {
            float2 s01 = upk2(accS0);
            float2 s23 = upk2(accS1);
            float2 s45 = upk2(accS2);
            int i0 = d0 * 32 + e;
            S[i0]       = S[i0] * el + s01.x;
            S[i0 + 32]  = S[i0 + 32] * el + s01.y;
            S[i0 + 64]  = S[i0 + 64] * el + s23.x;
            S[i0 + 96]  = S[i0 + 96] * el + s23.y;
            S[i0 + 128] = S[i0 + 128] * el + s45.x;
            S[i0 + 160] = S[i0 + 160] * el + s45.y;
        }
    }
}

// ---------------- gated RMS norm + transpose back (writes tf32 bits) ----------------
__global__ void gate_norm_kernel(const float* __restrict__ norm_w)
{
    int gw = (blockIdx.x * blockDim.x + threadIdx.x) >> 5;
    int lane = threadIdx.x & 31;
    if (gw >= cM * cH) return;
    int m = gw / cH, h = gw % cH;
    int b = m / cL, l = m % cL;
    const float* orow = g_o + ((size_t)(b * cH + h) * cL + l) * cDV;
    float vals[6];
    float ss = 0.f;
#pragma unroll
    for (int k = 0; k < 6; k++) {
        float v = orow[lane + 32 * k];
        vals[k] = v;
        ss += v * v;
    }
#pragma unroll
    for (int o = 16; o; o >>= 1) ss += __shfl_xor_sync(0xffffffffu, ss, o);
    float r = 1.f / sqrtf(ss / (float)cDV + 1e-5f);
#pragma unroll
    for (int k = 0; k < 6; k++) {
        int d = lane + 32 * k;
        float gg = g_proj[(size_t)m * cNP + 2 * cKD + cVD + h * cDV + d];
        float sg = gg / (1.f + expf(-gg));
        g_on[(size_t)m * cVD + h * cDV + d] = f2tf32(vals[k] * r * norm_w[d] * sg);
    }
}

// ---------------- host launch ----------------
template <typename T>
static T* sym(const void* symbol)
{
    void* p = nullptr;
    cudaGetSymbolAddress(&p, symbol);
    return (T*)p;
}

extern "C" void kernel_launch(void* const* d_in, const int* in_sizes, int n_in,
                              void* d_out, int out_size)
{
    const float* u       = (const float*)d_in[0];
    const float* Wq      = (const float*)d_in[1];
    const float* Wk      = (const float*)d_in[2];
    const float* Wv      = (const float*)d_in[3];
    const float* Wg      = (const float*)d_in[4];
    const float* Wo      = (const float*)d_in[5];
    const float* Wgk     = (const float*)d_in[6];
    const float* Wb      = (const float*)d_in[7];
    const float* b_b     = (const float*)d_in[8];
    const float* A_log   = (const float*)d_in[9];
    const float* dt_bias = (const float*)d_in[10];
    const float* conv_q  = (const float*)d_in[11];
    const float* conv_k  = (const float*)d_in[12];
    const float* conv_v  = (const float*)d_in[13];
    const float* norm_w  = (const float*)d_in[14];
    float* out = (float*)d_out;

    uint32_t* Wcat = sym<uint32_t>(g_Wcat);
    uint32_t* WoT  = sym<uint32_t>(g_WoT);
    uint32_t* uT   = sym<uint32_t>(g_uT);
    uint32_t* on   = sym<uint32_t>(g_on);
    float* proj = sym<float>(g_proj);

    cudaFuncSetAttribute(gemm_tf32_kernel, cudaFuncAttributeMaxDynamicSharedMemorySize, GEMM_SMEM);
    cudaFuncSetAttribute(chunk_pre_kernel, cudaFuncAttributeMaxDynamicSharedMemorySize,
                         CP_SMEM_FLOATS * (int)sizeof(float));
    cudaFuncSetAttribute(scan_kernel, cudaFuncAttributeMaxDynamicSharedMemorySize,
                         SC_SMEM_FLOATS * (int)sizeof(float));
    cudaFuncSetAttribute(proj_gates_kernel, cudaFuncAttributeMaxDynamicSharedMemorySize, 65536);

    // merged pack/convert (Wcat n-major | WoT n-major | u tf32)
    pack_all_kernel<<<(PK_TOT + 255) / 256, 256>>>(Wq, Wk, Wv, Wg, Wo, (const float4*)u);

    // fused projection GEMM (q|k|v|g)
    gemm_tf32_kernel<<<dim3(cNP / 128, cM / 128), 256, GEMM_SMEM>>>(
        uT, cD, Wcat, cD, proj, cNP, cM, cNP, cD);

    // gates
    proj_gates_kernel<<<cM / 8, 256, 65536>>>(u, Wgk, Wb, b_b, A_log, dt_bias);

    // fused conv+silu(+l2norm) -> head layouts
    conv_qk_norm_kernel<<<(cM * cH * 32 + 255) / 256, 256>>>(conv_q, conv_k);
    conv_v_kernel<<<(cM * cVD + 255) / 256, 256>>>(conv_v);

    // delta-rule chunk precompute (2 blocks/SM via smem overlay) + scan
    chunk_pre_kernel<<<cBH * cNC, CP_THREADS, CP_SMEM_FLOATS * sizeof(float)>>>();
    scan_kernel<<<dim3(6, cBH), SC_THREADS, SC_SMEM_FLOATS * sizeof(float)>>>();

    // gated rms norm + output projection
    gate_norm_kernel<<<(cM * cH * 32 + 255) / 256, 256>>>(norm_w);
    gemm_tf32_kernel<<<dim3(cD / 128, cM / 128), 256, GEMM_SMEM>>>(
        on, cVD, WoT, cVD, out, cD, cM, cD, cVD);
}